// round 15
// baseline (speedup 1.0000x reference)
#include <cuda_runtime.h>
#include <cstdint>
#include <cstddef>

#define T_TOK 4096
#define DMODEL 512
#define NHEAD 8
#define HDIM 64
#define FDIM 2048
#define NLAYER 6
#define SEQ 2048

// ---------------- scratch (static device globals; no allocation) ----------------
__device__ float g_h[T_TOK * DMODEL];
__device__ float g_htf[T_TOK * DMODEL];
__device__ float g_q[T_TOK * DMODEL];
__device__ float g_k[T_TOK * DMODEL];
__device__ float g_v[T_TOK * DMODEL];
__device__ float g_att[T_TOK * DMODEL];
__device__ float g_proj[T_TOK * DMODEL];
__device__ float g_ff[T_TOK * FDIM];
__device__ float g_wo_t[NLAYER * DMODEL * DMODEL];
__device__ float g_w1_t[NLAYER * FDIM * DMODEL];
__device__ float g_w2_t[NLAYER * DMODEL * FDIM];
__device__ float g_wqkv_t[NLAYER * 3 * HDIM * HDIM];

// ---------------- tf32 / cp.async helpers ----------------
__device__ __forceinline__ unsigned f2tf32(float f) {
    unsigned r;
    asm("cvt.rna.tf32.f32 %0, %1;" : "=r"(r) : "f"(f));
    return r;
}
__device__ __forceinline__ float f2tf32f(float f) { return __uint_as_float(f2tf32(f)); }

__device__ __forceinline__ void mma_tf32(float d[4], const unsigned a[4], const unsigned b[2]) {
    asm volatile(
        "mma.sync.aligned.m16n8k8.row.col.f32.tf32.tf32.f32 "
        "{%0,%1,%2,%3}, {%4,%5,%6,%7}, {%8,%9}, {%0,%1,%2,%3};"
        : "+f"(d[0]), "+f"(d[1]), "+f"(d[2]), "+f"(d[3])
        : "r"(a[0]), "r"(a[1]), "r"(a[2]), "r"(a[3]), "r"(b[0]), "r"(b[1]));
}

__device__ __forceinline__ void cp_async16(uint32_t dst, const void* src) {
    asm volatile("cp.async.ca.shared.global [%0], [%1], 16;" :: "r"(dst), "l"(src));
}
__device__ __forceinline__ void cp_commit() {
    asm volatile("cp.async.commit_group;");
}
template <int N>
__device__ __forceinline__ void cp_wait() {
    asm volatile("cp.async.wait_group %0;" :: "n"(N));
}

// ---------------- weight rounding (fp32 -> tf32 bits) ----------------
__global__ __launch_bounds__(256) void round_tf32_kernel(
    const float4* __restrict__ x, float4* __restrict__ y, int n4)
{
    int i = blockIdx.x * 256 + threadIdx.x;
    if (i < n4) {
        float4 v = x[i];
        v.x = f2tf32f(v.x); v.y = f2tf32f(v.y);
        v.z = f2tf32f(v.z); v.w = f2tf32f(v.w);
        y[i] = v;
    }
}

__global__ __launch_bounds__(256) void pack_qkv_weights_kernel(
    const float4* __restrict__ Wq, const float4* __restrict__ Wk,
    const float4* __restrict__ Wv, float4* __restrict__ dst)
{
    int i = blockIdx.x * 256 + threadIdx.x;
    int per = NLAYER * HDIM * HDIM / 4;
    if (i < per) {
        int l = i / (HDIM * HDIM / 4);
        int r = i % (HDIM * HDIM / 4);
        float4 vq = Wq[i], vk = Wk[i], vv = Wv[i];
        vq.x = f2tf32f(vq.x); vq.y = f2tf32f(vq.y); vq.z = f2tf32f(vq.z); vq.w = f2tf32f(vq.w);
        vk.x = f2tf32f(vk.x); vk.y = f2tf32f(vk.y); vk.z = f2tf32f(vk.z); vk.w = f2tf32f(vk.w);
        vv.x = f2tf32f(vv.x); vv.y = f2tf32f(vv.y); vv.z = f2tf32f(vv.z); vv.w = f2tf32f(vv.w);
        int base = l * 3 * (HDIM * HDIM / 4);
        dst[base + r] = vq;
        dst[base + (HDIM * HDIM / 4) + r] = vk;
        dst[base + 2 * (HDIM * HDIM / 4) + r] = vv;
    }
}

// ---------------- embedding (writes h and tf32-rounded htf) ----------------
__global__ __launch_bounds__(128) void embed_kernel(
    const int* __restrict__ src, const float* __restrict__ emb,
    float* __restrict__ h, float* __restrict__ htf)
{
    int t = blockIdx.x;
    int tok = src[t];
    const float4* e = (const float4*)(emb + (size_t)tok * DMODEL);
    const float s = 22.627416997969522f;  // sqrt(512)
    float4 v = e[threadIdx.x];
    v.x *= s; v.y *= s; v.z *= s; v.w *= s;
    ((float4*)(h + (size_t)t * DMODEL))[threadIdx.x] = v;
    float4 r;
    r.x = f2tf32f(v.x); r.y = f2tf32f(v.y);
    r.z = f2tf32f(v.z); r.w = f2tf32f(v.w);
    ((float4*)(htf + (size_t)t * DMODEL))[threadIdx.x] = r;
}

// ---------------- QKV via tf32 MMA (R12 proven) ----------------
#define QKV_LD 68

__global__ __launch_bounds__(256, 2) void qkv_mma_kernel(
    const float* __restrict__ A,
    const float* __restrict__ Wt,
    const float* __restrict__ bq, const float* __restrict__ bk, const float* __restrict__ bv,
    float* __restrict__ Q, float* __restrict__ K, float* __restrict__ V)
{
    extern __shared__ float sm[];
    float* A_s = sm;                       // [128][68]
    float* W_s = A_s + 128 * QKV_LD;       // [3][64][68]

    int tid = threadIdx.x;
    int warp = tid >> 5, lane = tid & 31;
    int g = lane >> 2, l4 = lane & 3;
    int wm = warp >> 1, wn = warp & 1;
    size_t r0 = (size_t)blockIdx.x * 128;

#pragma unroll
    for (int it = 0; it < 8; ++it) {
        int idx = tid + it * 256;
        int row = idx >> 4, q4 = idx & 15;
        uint32_t da = (uint32_t)__cvta_generic_to_shared(&A_s[row * QKV_LD + q4 * 4]);
        cp_async16(da, A + (r0 + row) * HDIM + q4 * 4);
    }
#pragma unroll
    for (int it = 0; it < 12; ++it) {
        int idx = tid + it * 256;
        int m = idx >> 10;
        int rem = idx & 1023;
        int row = rem >> 4, q4 = rem & 15;
        uint32_t dw = (uint32_t)__cvta_generic_to_shared(
            &W_s[m * 64 * QKV_LD + row * QKV_LD + q4 * 4]);
        cp_async16(dw, Wt + m * HDIM * HDIM + row * HDIM + q4 * 4);
    }
    cp_commit();
    cp_wait<0>();
    __syncthreads();

#pragma unroll
    for (int m = 0; m < 3; ++m) {
        const float* Ws = W_s + m * 64 * QKV_LD;
        float acc[2][4][4];
#pragma unroll
        for (int mi = 0; mi < 2; mi++)
#pragma unroll
            for (int ni = 0; ni < 4; ni++)
#pragma unroll
                for (int j = 0; j < 4; j++) acc[mi][ni][j] = 0.f;

#pragma unroll
        for (int ks = 0; ks < 8; ++ks) {
            int k = ks * 8;
            unsigned a[2][4], b[4][2];
#pragma unroll
            for (int mi = 0; mi < 2; mi++) {
                int rb = wm * 32 + mi * 16;
                a[mi][0] = __float_as_uint(A_s[(rb + g) * QKV_LD + k + l4]);
                a[mi][1] = __float_as_uint(A_s[(rb + g + 8) * QKV_LD + k + l4]);
                a[mi][2] = __float_as_uint(A_s[(rb + g) * QKV_LD + k + l4 + 4]);
                a[mi][3] = __float_as_uint(A_s[(rb + g + 8) * QKV_LD + k + l4 + 4]);
            }
#pragma unroll
            for (int ni = 0; ni < 4; ni++) {
                int nb = wn * 32 + ni * 8;
                b[ni][0] = __float_as_uint(Ws[(nb + g) * QKV_LD + k + l4]);
                b[ni][1] = __float_as_uint(Ws[(nb + g) * QKV_LD + k + l4 + 4]);
            }
#pragma unroll
            for (int mi = 0; mi < 2; mi++)
#pragma unroll
                for (int ni = 0; ni < 4; ni++)
                    mma_tf32(acc[mi][ni], a[mi], b[ni]);
        }

        const float* bias = (m == 0) ? bq : ((m == 1) ? bk : bv);
        float* outp = (m == 0) ? Q : ((m == 1) ? K : V);
#pragma unroll
        for (int ni = 0; ni < 4; ni++) {
            int c = wn * 32 + ni * 8 + l4 * 2;
            float b0 = bias[c], b1 = bias[c + 1];
#pragma unroll
            for (int mi = 0; mi < 2; mi++) {
                size_t rr0 = r0 + wm * 32 + mi * 16 + g;
                size_t rr1 = rr0 + 8;
                float2 v0 = {f2tf32f(acc[mi][ni][0] + b0), f2tf32f(acc[mi][ni][1] + b1)};
                float2 v1 = {f2tf32f(acc[mi][ni][2] + b0), f2tf32f(acc[mi][ni][3] + b1)};
                *(float2*)(outp + rr0 * HDIM + c) = v0;
                *(float2*)(outp + rr1 * HDIM + c) = v1;
            }
        }
    }
}

// ---------------- flash attention: V ping-pong (4 barriers/tile), float2 P stores ----------------
#define QK_LD 68
#define V_LD 72
#define P_LD 132

__global__ __launch_bounds__(256) void flash_kernel(
    const float* __restrict__ Qg, const float* __restrict__ Kg,
    const float* __restrict__ Vg, const int* __restrict__ mask,
    float* __restrict__ Og)
{
    extern __shared__ float sm[];
    float* Q_s  = sm;                     // [128][68]
    float* K_s  = Q_s + 128 * QK_LD;      // [128][68]
    float* V_s0 = K_s + 128 * QK_LD;      // [128][72]  ping
    float* V_s1 = V_s0 + 128 * V_LD;      // [128][72]  pong
    float* P_s  = V_s1 + 128 * V_LD;      // [128][132]
    float* mrow = P_s + 128 * P_LD;
    float* crow = mrow + 128;
    float* lrow = crow + 128;
    float* red  = lrow + 128;             // [128][4]
    int*   mkv  = (int*)(red + 512);      // [128]

    int tid = threadIdx.x;
    int warp = tid >> 5, lane = tid & 31;
    int g = lane >> 2, l4 = lane & 3;
    int wm = warp >> 2, wn = warp & 3;

    int qt = blockIdx.x, hh = blockIdx.y, n = blockIdx.z;
    int q0 = qt * 128;
    size_t baseQ  = ((size_t)(n * SEQ + q0)) * DMODEL + hh * HDIM;
    size_t baseKV = ((size_t)(n * SEQ)) * DMODEL + hh * HDIM;
    const int* maskbase = mask + n * SEQ;

    auto issueKM = [&](int kt) {
        size_t bK = baseKV + (size_t)(kt * 128) * DMODEL;
#pragma unroll
        for (int it = 0; it < 8; ++it) {
            int idx = tid + it * 256;
            int row = idx >> 4, q4 = idx & 15;
            uint32_t dk = (uint32_t)__cvta_generic_to_shared(&K_s[row * QK_LD + q4 * 4]);
            cp_async16(dk, Kg + bK + (size_t)row * DMODEL + q4 * 4);
        }
        if (tid < 32) {
            uint32_t dm = (uint32_t)__cvta_generic_to_shared(&mkv[tid * 4]);
            cp_async16(dm, maskbase + kt * 128 + tid * 4);
        }
    };
    auto issueV = [&](int kt) {
        float* Vb = (kt & 1) ? V_s1 : V_s0;
        size_t bK = baseKV + (size_t)(kt * 128) * DMODEL;
#pragma unroll
        for (int it = 0; it < 8; ++it) {
            int idx = tid + it * 256;
            int row = idx >> 4, q4 = idx & 15;
            uint32_t dv = (uint32_t)__cvta_generic_to_shared(&Vb[row * V_LD + q4 * 4]);
            cp_async16(dv, Vg + bK + (size_t)row * DMODEL + q4 * 4);
        }
    };

    issueKM(0); cp_commit();   // group: KM0
    issueV(0);  cp_commit();   // group: V0

#pragma unroll
    for (int it = 0; it < 8; ++it) {
        int idx = tid + it * 256;
        int row = idx >> 4, q4 = idx & 15;
        float4 v = *(const float4*)(Qg + baseQ + (size_t)row * DMODEL + q4 * 4);
        *(float4*)&Q_s[row * QK_LD + q4 * 4] = v;
    }
    if (tid < 128) { mrow[tid] = -3.0e38f; lrow[tid] = 0.f; }

    float o[4][2][4];
#pragma unroll
    for (int mi = 0; mi < 4; mi++)
#pragma unroll
        for (int ni = 0; ni < 2; ni++)
#pragma unroll
            for (int j = 0; j < 4; j++) o[mi][ni][j] = 0.f;

    const float INV    = 0.04419417382415922f;   // 1/sqrt(512)
    const float MASKED = -1e10f * 0.04419417382415922f;

    for (int kt = 0; kt < 16; ++kt) {
        // pending (per-thread, commit order): KM(kt), V(kt) -> <=1 completes KM(kt)
        cp_wait<1>();
        __syncthreads();   // A: K_s/mkv (and Q_s on kt==0; V(kt-1) buffer free) visible

        // ---- S = Q @ K^T ----
        float s[4][4][4];
#pragma unroll
        for (int mi = 0; mi < 4; mi++)
#pragma unroll
            for (int ni = 0; ni < 4; ni++)
#pragma unroll
                for (int j = 0; j < 4; j++) s[mi][ni][j] = 0.f;

#pragma unroll
        for (int ks = 0; ks < 8; ++ks) {
            int k = ks * 8;
            unsigned a[4][4], b[4][2];
#pragma unroll
            for (int mi = 0; mi < 4; mi++) {
                int rb = wm * 64 + mi * 16;
                a[mi][0] = __float_as_uint(Q_s[(rb + g) * QK_LD + k + l4]);
                a[mi][1] = __float_as_uint(Q_s[(rb + g + 8) * QK_LD + k + l4]);
                a[mi][2] = __float_as_uint(Q_s[(rb + g) * QK_LD + k + l4 + 4]);
                a[mi][3] = __float_as_uint(Q_s[(rb + g + 8) * QK_LD + k + l4 + 4]);
            }
#pragma unroll
            for (int ni = 0; ni < 4; ni++) {
                int nb = wn * 32 + ni * 8;
                b[ni][0] = __float_as_uint(K_s[(nb + g) * QK_LD + k + l4]);
                b[ni][1] = __float_as_uint(K_s[(nb + g) * QK_LD + k + l4 + 4]);
            }
#pragma unroll
            for (int mi = 0; mi < 4; mi++)
#pragma unroll
                for (int ni = 0; ni < 4; ni++)
                    mma_tf32(s[mi][ni], a[mi], b[ni]);
        }

        // ---- mask + scale, per-thread row maxes ----
        float m0v[4], m1v[4];
#pragma unroll
        for (int mi = 0; mi < 4; mi++) { m0v[mi] = -3.0e38f; m1v[mi] = -3.0e38f; }
#pragma unroll
        for (int ni = 0; ni < 4; ni++) {
            int c = wn * 32 + ni * 8 + l4 * 2;
            bool z0 = (mkv[c] == 0), z1 = (mkv[c + 1] == 0);
#pragma unroll
            for (int mi = 0; mi < 4; mi++) {
                s[mi][ni][0] = z0 ? MASKED : s[mi][ni][0] * INV;
                s[mi][ni][1] = z1 ? MASKED : s[mi][ni][1] * INV;
                s[mi][ni][2] = z0 ? MASKED : s[mi][ni][2] * INV;
                s[mi][ni][3] = z1 ? MASKED : s[mi][ni][3] * INV;
                m0v[mi] = fmaxf(m0v[mi], fmaxf(s[mi][ni][0], s[mi][ni][1]));
                m1v[mi] = fmaxf(m1v[mi], fmaxf(s[mi][ni][2], s[mi][ni][3]));
            }
        }
#pragma unroll
        for (int mi = 0; mi < 4; mi++) {
            m0v[mi] = fmaxf(m0v[mi], __shfl_xor_sync(0xffffffffu, m0v[mi], 1));
            m0v[mi] = fmaxf(m0v[mi], __shfl_xor_sync(0xffffffffu, m0v[mi], 2));
            m1v[mi] = fmaxf(m1v[mi], __shfl_xor_sync(0xffffffffu, m1v[mi], 1));
            m1v[mi] = fmaxf(m1v[mi], __shfl_xor_sync(0xffffffffu, m1v[mi], 2));
            if (l4 == 0) {
                int r0 = wm * 64 + mi * 16 + g;
                red[r0 * 4 + wn] = m0v[mi];
                red[(r0 + 8) * 4 + wn] = m1v[mi];
            }
        }
        __syncthreads();   // B: tile maxes done; K_s/mkv consumed

        if (kt < 15) { issueKM(kt + 1); cp_commit(); }

        if (tid < 128) {
            float mo = mrow[tid];
            float mx = fmaxf(fmaxf(red[tid * 4 + 0], red[tid * 4 + 1]),
                             fmaxf(red[tid * 4 + 2], red[tid * 4 + 3]));
            mx = fmaxf(mo, mx);
            crow[tid] = __expf(mo - mx);
            mrow[tid] = mx;
        }
        __syncthreads();   // C

        // ---- P = exp(s - mrow) -> smem (tf32, float2 stores), partial row sums ----
#pragma unroll
        for (int mi = 0; mi < 4; mi++) {
            int r0 = wm * 64 + mi * 16 + g;
            int r1 = r0 + 8;
            float mr0 = mrow[r0], mr1 = mrow[r1];
            float ps0 = 0.f, ps1 = 0.f;
#pragma unroll
            for (int ni = 0; ni < 4; ni++) {
                int c = wn * 32 + ni * 8 + l4 * 2;
                float p00 = __expf(s[mi][ni][0] - mr0);
                float p01 = __expf(s[mi][ni][1] - mr0);
                float p10 = __expf(s[mi][ni][2] - mr1);
                float p11 = __expf(s[mi][ni][3] - mr1);
                ps0 += p00 + p01;
                ps1 += p10 + p11;
                float2 w0 = {f2tf32f(p00), f2tf32f(p01)};
                float2 w1 = {f2tf32f(p10), f2tf32f(p11)};
                *(float2*)&P_s[r0 * P_LD + c] = w0;
                *(float2*)&P_s[r1 * P_LD + c] = w1;
            }
            ps0 += __shfl_xor_sync(0xffffffffu, ps0, 1);
            ps0 += __shfl_xor_sync(0xffffffffu, ps0, 2);
            ps1 += __shfl_xor_sync(0xffffffffu, ps1, 1);
            ps1 += __shfl_xor_sync(0xffffffffu, ps1, 2);
            if (l4 == 0) {
                red[r0 * 4 + wn] = ps0;
                red[r1 * 4 + wn] = ps1;
            }
            float c0 = crow[r0], c1 = crow[r1];
#pragma unroll
            for (int ni = 0; ni < 2; ni++) {
                o[mi][ni][0] *= c0; o[mi][ni][1] *= c0;
                o[mi][ni][2] *= c1; o[mi][ni][3] *= c1;
            }
        }

        // wait V(kt); pending: {V(kt), KM(kt+1)} -> <=1 completes V(kt); last tile -> <=0
        if (kt < 15) cp_wait<1>(); else cp_wait<0>();
        __syncthreads();   // D: P_s + sums + V_s(kt&1) visible

        if (tid < 128) {
            float s2 = red[tid * 4 + 0] + red[tid * 4 + 1] + red[tid * 4 + 2] + red[tid * 4 + 3];
            lrow[tid] = lrow[tid] * crow[tid] + s2;
        }

        // prefetch next V into the OTHER buffer (overlaps with PV below; no barrier needed)
        if (kt < 15) { issueV(kt + 1); cp_commit(); }

        // ---- O += P @ V (reads V buffer kt&1) ----
        const float* Vs = (kt & 1) ? V_s1 : V_s0;
#pragma unroll
        for (int ks = 0; ks < 16; ++ks) {
            int k = ks * 8;
            unsigned a[4][4], b[2][2];
#pragma unroll
            for (int mi = 0; mi < 4; mi++) {
                int rb = wm * 64 + mi * 16;
                a[mi][0] = __float_as_uint(P_s[(rb + g) * P_LD + k + l4]);
                a[mi][1] = __float_as_uint(P_s[(rb + g + 8) * P_LD + k + l4]);
                a[mi][2] = __float_as_uint(P_s[(rb + g) * P_LD + k + l4 + 4]);
                a[mi][3] = __float_as_uint(P_s[(rb + g + 8) * P_LD + k + l4 + 4]);
            }
#pragma unroll
            for (int ni = 0; ni < 2; ni++) {
                int cb = wn * 16 + ni * 8;
                b[ni][0] = __float_as_uint(Vs[(k + l4) * V_LD + cb + g]);
                b[ni][1] = __float_as_uint(Vs[(k + l4 + 4) * V_LD + cb + g]);
            }
#pragma unroll
            for (int mi = 0; mi < 4; mi++)
#pragma unroll
                for (int ni = 0; ni < 2; ni++)
                    mma_tf32(o[mi][ni], a[mi], b[ni]);
        }
        // no barrier E: next-iter barrier A orders P_s reuse; V is double-buffered
    }

#pragma unroll
    for (int mi = 0; mi < 4; mi++) {
        int r0 = wm * 64 + mi * 16 + g;
        int r1 = r0 + 8;
        float li0 = 1.f / lrow[r0];
        float li1 = 1.f / lrow[r1];
#pragma unroll
        for (int ni = 0; ni < 2; ni++) {
            int c = wn * 16 + ni * 8 + l4 * 2;
            float2 v0 = {f2tf32f(o[mi][ni][0] * li0), f2tf32f(o[mi][ni][1] * li0)};
            float2 v1 = {f2tf32f(o[mi][ni][2] * li1), f2tf32f(o[mi][ni][3] * li1)};
            *(float2*)(Og + baseQ + (size_t)r0 * DMODEL + c) = v0;
            *(float2*)(Og + baseQ + (size_t)r1 * DMODEL + c) = v1;
        }
    }
}

// ---------------- pipelined tf32 GEMM (R12 config): 128x128x32, 3-stage ----------------
#define G_LD 36
#define G_STG (128 * G_LD)

__device__ __forceinline__ void load_frags(
    const float* __restrict__ As, const float* __restrict__ Bs, int k,
    int wm, int wn, int g, int l4,
    unsigned a[4][4], unsigned b[4][2])
{
#pragma unroll
    for (int mi = 0; mi < 4; mi++) {
        int rb = wm * 64 + mi * 16;
        a[mi][0] = __float_as_uint(As[(rb + g) * G_LD + k + l4]);
        a[mi][1] = __float_as_uint(As[(rb + g + 8) * G_LD + k + l4]);
        a[mi][2] = __float_as_uint(As[(rb + g) * G_LD + k + l4 + 4]);
        a[mi][3] = __float_as_uint(As[(rb + g + 8) * G_LD + k + l4 + 4]);
    }
#pragma unroll
    for (int ni = 0; ni < 4; ni++) {
        int nb = wn * 32 + ni * 8;
        b[ni][0] = __float_as_uint(Bs[(nb + g) * G_LD + k + l4]);
        b[ni][1] = __float_as_uint(Bs[(nb + g) * G_LD + k + l4 + 4]);
    }
}

template <bool RELU, bool ROUND_OUT>
__global__ __launch_bounds__(256) void sgemm_tf32_pipe(
    const float* __restrict__ A, const float* __restrict__ B,
    const float* __restrict__ bias, float* __restrict__ C,
    int M, int N, int K)
{
    extern __shared__ float smem[];
    int tid = threadIdx.x;
    int warp = tid >> 5, lane = tid & 31;
    int g = lane >> 2, l4 = lane & 3;
    int wm = warp >> 2, wn = warp & 3;
    int n0 = blockIdx.x * 128, m0 = blockIdx.y * 128;

    int crow = tid >> 3;
    int ccol = (tid & 7) * 4;

    const float* Abase = A + (size_t)m0 * K;
    const float* Bbase = B + (size_t)n0 * K;

    auto issue = [&](int s, int kb) {
        float* As = smem + s * 2 * G_STG;
        float* Bs = As + G_STG;
#pragma unroll
        for (int it = 0; it < 4; ++it) {
            int row = crow + it * 32;
            uint32_t da = (uint32_t)__cvta_generic_to_shared(&As[row * G_LD + ccol]);
            cp_async16(da, Abase + (size_t)row * K + kb + ccol);
            uint32_t db = (uint32_t)__cvta_generic_to_shared(&Bs[row * G_LD + ccol]);
            cp_async16(db, Bbase + (size_t)row * K + kb + ccol);
        }
    };

    float acc[4][4][4];
#pragma unroll
    for (int mi = 0; mi < 4; mi++)
#pragma unroll
        for (int ni = 0; ni < 4; ni++)
#pragma unroll
            for (int j = 0; j < 4; j++) acc[mi][ni][j] = 0.f;

    int nt = K >> 5;
    issue(0, 0);  cp_commit();
    issue(1, 32); cp_commit();
    cp_wait<1>();
    __syncthreads();

    for (int t = 0; t < nt; ++t) {
        int st = t % 3;
        if (t + 2 < nt) { issue((t + 2) % 3, (t + 2) * 32); cp_commit(); }

        const float* As = smem + st * 2 * G_STG;
        const float* Bs = As + G_STG;

        unsigned afr[2][4][4], bfr[2][4][2];
        load_frags(As, Bs, 0, wm, wn, g, l4, afr[0], bfr[0]);
#pragma unroll
        for (int ks = 0; ks < 4; ++ks) {
            if (ks < 3)
                load_frags(As, Bs, (ks + 1) * 8, wm, wn, g, l4,
                           afr[(ks + 1) & 1], bfr[(ks + 1) & 1]);
#pragma unroll
            for (int mi = 0; mi < 4; mi++)
#pragma unroll
                for (int ni = 0; ni < 4; ni++)
                    mma_tf32(acc[mi][ni], afr[ks & 1][mi], bfr[ks & 1][ni]);
        }

        if (t + 2 < nt) cp_wait<1>();
        else            cp_wait<0>();
        __syncthreads();
    }

#pragma unroll
    for (int ni = 0; ni < 4; ni++) {
        int c = n0 + wn * 32 + ni * 8 + l4 * 2;
        float b0 = bias[c], b1 = bias[c + 1];
#pragma unroll
        for (int mi = 0; mi < 4; mi++) {
            int r0 = m0 + wm * 64 + mi * 16 + g;
            int r1 = r0 + 8;
            float2 v0 = {acc[mi][ni][0] + b0, acc[mi][ni][1] + b1};
            float2 v1 = {acc[mi][ni][2] + b0, acc[mi][ni][3] + b1};
            if (RELU) {
                v0.x = fmaxf(v0.x, 0.f); v0.y = fmaxf(v0.y, 0.f);
                v1.x = fmaxf(v1.x, 0.f); v1.y = fmaxf(v1.y, 0.f);
            }
            if (ROUND_OUT) {
                v0.x = f2tf32f(v0.x); v0.y = f2tf32f(v0.y);
                v1.x = f2tf32f(v1.x); v1.y = f2tf32f(v1.y);
            }
            *(float2*)(C + (size_t)r0 * N + c) = v0;
            *(float2*)(C + (size_t)r1 * N + c) = v1;
        }
    }
}

// ---------------- fused residual-add + LayerNorm (+ optional tf32 copy) ----------------
__global__ __launch_bounds__(128) void add_ln_kernel(
    const float* __restrict__ x, const float* __restrict__ a,
    const float* __restrict__ g, const float* __restrict__ b,
    float* __restrict__ dst, float* __restrict__ dst_tf)
{
    int t = blockIdx.x, tid = threadIdx.x;
    float4 v  = ((const float4*)(x + (size_t)t * DMODEL))[tid];
    float4 av = ((const float4*)(a + (size_t)t * DMODEL))[tid];
    v.x += av.x; v.y += av.y; v.z += av.z; v.w += av.w;
    float s  = v.x + v.y + v.z + v.w;
    float sq = v.x * v.x + v.y * v.y + v.z * v.z + v.w * v.w;
#pragma unroll
    for (int o = 16; o > 0; o >>= 1) {
        s  += __shfl_xor_sync(0xffffffffu, s,  o);
        sq += __shfl_xor_sync(0xffffffffu, sq, o);
    }
    __shared__ float ws[4], wq[4];
    int warp = tid >> 5, lane = tid & 31;
    if (lane == 0) { ws[warp] = s; wq[warp] = sq; }
    __syncthreads();
    s  = ws[0] + ws[1] + ws[2] + ws[3];
    sq = wq[0] + wq[1] + wq[2] + wq[3];
    float mean = s * (1.f / 512.f);
    float var  = sq * (1.f / 512.f) - mean * mean;
    float rs = rsqrtf(var + 1e-5f);
    float4 gg  = ((const float4*)g)[tid];
    float4 bb2 = ((const float4*)b)[tid];
    float4 o4;
    o4.x = (v.x - mean) * rs * gg.x + bb2.x;
    o4.y = (v.y - mean) * rs * gg.y + bb2.y;
    o4.z = (v.z - mean) * rs * gg.z + bb2.z;
    o4.w = (v.w - mean) * rs * gg.w + bb2.w;
    ((float4*)(dst + (size_t)t * DMODEL))[tid] = o4;
    if (dst_tf) {
        float4 r4;
        r4.x = f2tf32f(o4.x); r4.y = f2tf32f(o4.y);
        r4.z = f2tf32f(o4.z); r4.w = f2tf32f(o4.w);
        ((float4*)(dst_tf + (size_t)t * DMODEL))[tid] = r4;
    }
}

// ---------------- launcher ----------------
extern "C" void kernel_launch(void* const* d_in, const int* in_sizes, int n_in,
                              void* d_out, int out_size)
{
    const int*   src  = (const int*)d_in[0];
    const int*   mask = (const int*)d_in[1];
    const float* emb = (const float*)d_in[2];
    const float* Wq  = (const float*)d_in[3];
    const float* bq  = (const float*)d_in[4];
    const float* Wk  = (const float*)d_in[5];
    const float* bk  = (const float*)d_in[6];
    const float* Wv  = (const float*)d_in[7];
    const float* bv  = (const float*)d_in[8];
    const float* Wo  = (const float*)d_in[9];
    const float* bo  = (const float*)d_in[10];
    const float* W1  = (const float*)d_in[11];
    const float* b1  = (const float*)d_in[12];
    const float* W2  = (const float*)d_in[13];
    const float* b2  = (const float*)d_in[14];
    const float* ln1g = (const float*)d_in[15];
    const float* ln1b = (const float*)d_in[16];
    const float* ln2g = (const float*)d_in[17];
    const float* ln2b = (const float*)d_in[18];
    float* out = (float*)d_out;

    float *h, *htf, *q, *k, *v, *att, *proj, *ff, *woT, *w1T, *w2T, *wqkvT;
    cudaGetSymbolAddress((void**)&h,    g_h);
    cudaGetSymbolAddress((void**)&htf,  g_htf);
    cudaGetSymbolAddress((void**)&q,    g_q);
    cudaGetSymbolAddress((void**)&k,    g_k);
    cudaGetSymbolAddress((void**)&v,    g_v);
    cudaGetSymbolAddress((void**)&att,  g_att);
    cudaGetSymbolAddress((void**)&proj, g_proj);
    cudaGetSymbolAddress((void**)&ff,   g_ff);
    cudaGetSymbolAddress((void**)&woT,  g_wo_t);
    cudaGetSymbolAddress((void**)&w1T,  g_w1_t);
    cudaGetSymbolAddress((void**)&w2T,  g_w2_t);
    cudaGetSymbolAddress((void**)&wqkvT, g_wqkv_t);

    // flash smem: 2*128*68 + 2*128*72 + 128*132 + 3*128 + 512 + 128 floats = 215,040 B
    const size_t flashSmem = (size_t)(2 * 128 * QK_LD + 2 * 128 * V_LD + 128 * P_LD
                                      + 3 * 128 + 512 + 128) * sizeof(float);
    cudaFuncSetAttribute(flash_kernel, cudaFuncAttributeMaxDynamicSharedMemorySize,
                         (int)flashSmem);
    const size_t gemmSmem = (size_t)3 * 2 * G_STG * sizeof(float);   // 110,592 B
    cudaFuncSetAttribute(sgemm_tf32_pipe<false, false>,
                         cudaFuncAttributeMaxDynamicSharedMemorySize, (int)gemmSmem);
    cudaFuncSetAttribute(sgemm_tf32_pipe<true, true>,
                         cudaFuncAttributeMaxDynamicSharedMemorySize, (int)gemmSmem);
    const size_t qkvSmem = (size_t)(128 + 3 * 64) * QKV_LD * sizeof(float);
    cudaFuncSetAttribute(qkv_mma_kernel, cudaFuncAttributeMaxDynamicSharedMemorySize,
                         (int)qkvSmem);

    // pre-round all GEMM weights to tf32
    {
        int n4;
        n4 = NLAYER * DMODEL * DMODEL / 4;
        round_tf32_kernel<<<(n4 + 255) / 256, 256>>>((const float4*)Wo, (float4*)woT, n4);
        n4 = NLAYER * FDIM * DMODEL / 4;
        round_tf32_kernel<<<(n4 + 255) / 256, 256>>>((const float4*)W1, (float4*)w1T, n4);
        round_tf32_kernel<<<(n4 + 255) / 256, 256>>>((const float4*)W2, (float4*)w2T, n4);
        int nq = NLAYER * HDIM * HDIM / 4;
        pack_qkv_weights_kernel<<<(nq + 255) / 256, 256>>>(
            (const float4*)Wq, (const float4*)Wk, (const float4*)Wv, (float4*)wqkvT);
    }

    embed_kernel<<<T_TOK, 128>>>(src, emb, h, htf);

    for (int l = 0; l < NLAYER; ++l) {
        qkv_mma_kernel<<<256, 256, qkvSmem>>>(htf,
            wqkvT + (size_t)l * 3 * HDIM * HDIM,
            bq + l * HDIM, bk + l * HDIM, bv + l * HDIM,
            q, k, v);

        flash_kernel<<<dim3(16, NHEAD, 2), 256, flashSmem>>>(q, k, v, mask, att);

        sgemm_tf32_pipe<false, false><<<dim3(4, 32), 256, gemmSmem>>>(
            att, woT + (size_t)l * DMODEL * DMODEL, bo + l * DMODEL, proj,
            T_TOK, DMODEL, DMODEL);

        add_ln_kernel<<<T_TOK, 128>>>(h, proj, ln1g + l * DMODEL, ln1b + l * DMODEL,
                                      h, htf);

        sgemm_tf32_pipe<true, true><<<dim3(16, 32), 256, gemmSmem>>>(
            htf, w1T + (size_t)l * FDIM * DMODEL, b1 + l * FDIM, ff,
            T_TOK, FDIM, DMODEL);

        sgemm_tf32_pipe<false, false><<<dim3(4, 32), 256, gemmSmem>>>(
            ff, w2T + (size_t)l * DMODEL * FDIM, b2 + l * DMODEL, proj,
            T_TOK, DMODEL, FDIM);

        add_ln_kernel<<<T_TOK, 128>>>(h, proj, ln2g + l * DMODEL, ln2b + l * DMODEL,
                                      (l == NLAYER - 1) ? out : h,
                                      (l == NLAYER - 1) ? (float*)nullptr : htf);
    }
}

// round 16
// speedup vs baseline: 1.0208x; 1.0208x over previous
#include <cuda_runtime.h>
#include <cstdint>
#include <cstddef>

#define T_TOK 4096
#define DMODEL 512
#define NHEAD 8
#define HDIM 64
#define FDIM 2048
#define NLAYER 6
#define SEQ 2048

// ---------------- scratch (static device globals; no allocation) ----------------
__device__ float g_h[T_TOK * DMODEL];
__device__ float g_htf[T_TOK * DMODEL];
__device__ float g_q[T_TOK * DMODEL];
__device__ float g_k[T_TOK * DMODEL];
__device__ float g_v[T_TOK * DMODEL];
__device__ float g_att[T_TOK * DMODEL];
__device__ float g_proj[T_TOK * DMODEL];
__device__ float g_ff[T_TOK * FDIM];
__device__ float g_wo_t[NLAYER * DMODEL * DMODEL];
__device__ float g_w1_t[NLAYER * FDIM * DMODEL];
__device__ float g_w2_t[NLAYER * DMODEL * FDIM];
__device__ float g_wqkv_t[NLAYER * 3 * HDIM * HDIM];

// ---------------- tf32 / cp.async helpers ----------------
__device__ __forceinline__ unsigned f2tf32(float f) {
    unsigned r;
    asm("cvt.rna.tf32.f32 %0, %1;" : "=r"(r) : "f"(f));
    return r;
}
__device__ __forceinline__ float f2tf32f(float f) { return __uint_as_float(f2tf32(f)); }

__device__ __forceinline__ void mma_tf32(float d[4], const unsigned a[4], const unsigned b[2]) {
    asm volatile(
        "mma.sync.aligned.m16n8k8.row.col.f32.tf32.tf32.f32 "
        "{%0,%1,%2,%3}, {%4,%5,%6,%7}, {%8,%9}, {%0,%1,%2,%3};"
        : "+f"(d[0]), "+f"(d[1]), "+f"(d[2]), "+f"(d[3])
        : "r"(a[0]), "r"(a[1]), "r"(a[2]), "r"(a[3]), "r"(b[0]), "r"(b[1]));
}

__device__ __forceinline__ void cp_async16(uint32_t dst, const void* src) {
    asm volatile("cp.async.ca.shared.global [%0], [%1], 16;" :: "r"(dst), "l"(src));
}
__device__ __forceinline__ void cp_commit() {
    asm volatile("cp.async.commit_group;");
}
template <int N>
__device__ __forceinline__ void cp_wait() {
    asm volatile("cp.async.wait_group %0;" :: "n"(N));
}

// ---------------- weight rounding (fp32 -> tf32 bits) ----------------
__global__ __launch_bounds__(256) void round_tf32_kernel(
    const float4* __restrict__ x, float4* __restrict__ y, int n4)
{
    int i = blockIdx.x * 256 + threadIdx.x;
    if (i < n4) {
        float4 v = x[i];
        v.x = f2tf32f(v.x); v.y = f2tf32f(v.y);
        v.z = f2tf32f(v.z); v.w = f2tf32f(v.w);
        y[i] = v;
    }
}

__global__ __launch_bounds__(256) void pack_qkv_weights_kernel(
    const float4* __restrict__ Wq, const float4* __restrict__ Wk,
    const float4* __restrict__ Wv, float4* __restrict__ dst)
{
    int i = blockIdx.x * 256 + threadIdx.x;
    int per = NLAYER * HDIM * HDIM / 4;
    if (i < per) {
        int l = i / (HDIM * HDIM / 4);
        int r = i % (HDIM * HDIM / 4);
        float4 vq = Wq[i], vk = Wk[i], vv = Wv[i];
        vq.x = f2tf32f(vq.x); vq.y = f2tf32f(vq.y); vq.z = f2tf32f(vq.z); vq.w = f2tf32f(vq.w);
        vk.x = f2tf32f(vk.x); vk.y = f2tf32f(vk.y); vk.z = f2tf32f(vk.z); vk.w = f2tf32f(vk.w);
        vv.x = f2tf32f(vv.x); vv.y = f2tf32f(vv.y); vv.z = f2tf32f(vv.z); vv.w = f2tf32f(vv.w);
        int base = l * 3 * (HDIM * HDIM / 4);
        dst[base + r] = vq;
        dst[base + (HDIM * HDIM / 4) + r] = vk;
        dst[base + 2 * (HDIM * HDIM / 4) + r] = vv;
    }
}

// ---------------- embedding (writes h and tf32-rounded htf) ----------------
__global__ __launch_bounds__(128) void embed_kernel(
    const int* __restrict__ src, const float* __restrict__ emb,
    float* __restrict__ h, float* __restrict__ htf)
{
    int t = blockIdx.x;
    int tok = src[t];
    const float4* e = (const float4*)(emb + (size_t)tok * DMODEL);
    const float s = 22.627416997969522f;  // sqrt(512)
    float4 v = e[threadIdx.x];
    v.x *= s; v.y *= s; v.z *= s; v.w *= s;
    ((float4*)(h + (size_t)t * DMODEL))[threadIdx.x] = v;
    float4 r;
    r.x = f2tf32f(v.x); r.y = f2tf32f(v.y);
    r.z = f2tf32f(v.z); r.w = f2tf32f(v.w);
    ((float4*)(htf + (size_t)t * DMODEL))[threadIdx.x] = r;
}

// ---------------- QKV via tf32 MMA (R12 proven) ----------------
#define QKV_LD 68

__global__ __launch_bounds__(256, 2) void qkv_mma_kernel(
    const float* __restrict__ A,
    const float* __restrict__ Wt,
    const float* __restrict__ bq, const float* __restrict__ bk, const float* __restrict__ bv,
    float* __restrict__ Q, float* __restrict__ K, float* __restrict__ V)
{
    extern __shared__ float sm[];
    float* A_s = sm;                       // [128][68]
    float* W_s = A_s + 128 * QKV_LD;       // [3][64][68]

    int tid = threadIdx.x;
    int warp = tid >> 5, lane = tid & 31;
    int g = lane >> 2, l4 = lane & 3;
    int wm = warp >> 1, wn = warp & 1;
    size_t r0 = (size_t)blockIdx.x * 128;

#pragma unroll
    for (int it = 0; it < 8; ++it) {
        int idx = tid + it * 256;
        int row = idx >> 4, q4 = idx & 15;
        uint32_t da = (uint32_t)__cvta_generic_to_shared(&A_s[row * QKV_LD + q4 * 4]);
        cp_async16(da, A + (r0 + row) * HDIM + q4 * 4);
    }
#pragma unroll
    for (int it = 0; it < 12; ++it) {
        int idx = tid + it * 256;
        int m = idx >> 10;
        int rem = idx & 1023;
        int row = rem >> 4, q4 = rem & 15;
        uint32_t dw = (uint32_t)__cvta_generic_to_shared(
            &W_s[m * 64 * QKV_LD + row * QKV_LD + q4 * 4]);
        cp_async16(dw, Wt + m * HDIM * HDIM + row * HDIM + q4 * 4);
    }
    cp_commit();
    cp_wait<0>();
    __syncthreads();

#pragma unroll
    for (int m = 0; m < 3; ++m) {
        const float* Ws = W_s + m * 64 * QKV_LD;
        float acc[2][4][4];
#pragma unroll
        for (int mi = 0; mi < 2; mi++)
#pragma unroll
            for (int ni = 0; ni < 4; ni++)
#pragma unroll
                for (int j = 0; j < 4; j++) acc[mi][ni][j] = 0.f;

#pragma unroll
        for (int ks = 0; ks < 8; ++ks) {
            int k = ks * 8;
            unsigned a[2][4], b[4][2];
#pragma unroll
            for (int mi = 0; mi < 2; mi++) {
                int rb = wm * 32 + mi * 16;
                a[mi][0] = __float_as_uint(A_s[(rb + g) * QKV_LD + k + l4]);
                a[mi][1] = __float_as_uint(A_s[(rb + g + 8) * QKV_LD + k + l4]);
                a[mi][2] = __float_as_uint(A_s[(rb + g) * QKV_LD + k + l4 + 4]);
                a[mi][3] = __float_as_uint(A_s[(rb + g + 8) * QKV_LD + k + l4 + 4]);
            }
#pragma unroll
            for (int ni = 0; ni < 4; ni++) {
                int nb = wn * 32 + ni * 8;
                b[ni][0] = __float_as_uint(Ws[(nb + g) * QKV_LD + k + l4]);
                b[ni][1] = __float_as_uint(Ws[(nb + g) * QKV_LD + k + l4 + 4]);
            }
#pragma unroll
            for (int mi = 0; mi < 2; mi++)
#pragma unroll
                for (int ni = 0; ni < 4; ni++)
                    mma_tf32(acc[mi][ni], a[mi], b[ni]);
        }

        const float* bias = (m == 0) ? bq : ((m == 1) ? bk : bv);
        float* outp = (m == 0) ? Q : ((m == 1) ? K : V);
#pragma unroll
        for (int ni = 0; ni < 4; ni++) {
            int c = wn * 32 + ni * 8 + l4 * 2;
            float b0 = bias[c], b1 = bias[c + 1];
#pragma unroll
            for (int mi = 0; mi < 2; mi++) {
                size_t rr0 = r0 + wm * 32 + mi * 16 + g;
                size_t rr1 = rr0 + 8;
                float2 v0 = {f2tf32f(acc[mi][ni][0] + b0), f2tf32f(acc[mi][ni][1] + b1)};
                float2 v1 = {f2tf32f(acc[mi][ni][2] + b0), f2tf32f(acc[mi][ni][3] + b1)};
                *(float2*)(outp + rr0 * HDIM + c) = v0;
                *(float2*)(outp + rr1 * HDIM + c) = v1;
            }
        }
    }
}

// ---------------- flash attention (R14 proven: async K/V, V_LD=72) ----------------
#define QK_LD 68
#define V_LD 72
#define P_LD 132

__global__ __launch_bounds__(256) void flash_kernel(
    const float* __restrict__ Qg, const float* __restrict__ Kg,
    const float* __restrict__ Vg, const int* __restrict__ mask,
    float* __restrict__ Og)
{
    extern __shared__ float sm[];
    float* Q_s  = sm;                     // [128][68]
    float* K_s  = Q_s + 128 * QK_LD;      // [128][68]
    float* V_s  = K_s + 128 * QK_LD;      // [128][72]
    float* P_s  = V_s + 128 * V_LD;       // [128][132]
    float* mrow = P_s + 128 * P_LD;
    float* crow = mrow + 128;
    float* lrow = crow + 128;
    float* red  = lrow + 128;             // [128][4]
    int*   mkv  = (int*)(red + 512);      // [128]

    int tid = threadIdx.x;
    int warp = tid >> 5, lane = tid & 31;
    int g = lane >> 2, l4 = lane & 3;
    int wm = warp >> 2, wn = warp & 3;

    int qt = blockIdx.x, hh = blockIdx.y, n = blockIdx.z;
    int q0 = qt * 128;
    size_t baseQ  = ((size_t)(n * SEQ + q0)) * DMODEL + hh * HDIM;
    size_t baseKV = ((size_t)(n * SEQ)) * DMODEL + hh * HDIM;
    const int* maskbase = mask + n * SEQ;

    auto issueKM = [&](int kt) {
        size_t bK = baseKV + (size_t)(kt * 128) * DMODEL;
#pragma unroll
        for (int it = 0; it < 8; ++it) {
            int idx = tid + it * 256;
            int row = idx >> 4, q4 = idx & 15;
            uint32_t dk = (uint32_t)__cvta_generic_to_shared(&K_s[row * QK_LD + q4 * 4]);
            cp_async16(dk, Kg + bK + (size_t)row * DMODEL + q4 * 4);
        }
        if (tid < 32) {
            uint32_t dm = (uint32_t)__cvta_generic_to_shared(&mkv[tid * 4]);
            cp_async16(dm, maskbase + kt * 128 + tid * 4);
        }
    };
    auto issueV = [&](int kt) {
        size_t bK = baseKV + (size_t)(kt * 128) * DMODEL;
#pragma unroll
        for (int it = 0; it < 8; ++it) {
            int idx = tid + it * 256;
            int row = idx >> 4, q4 = idx & 15;
            uint32_t dv = (uint32_t)__cvta_generic_to_shared(&V_s[row * V_LD + q4 * 4]);
            cp_async16(dv, Vg + bK + (size_t)row * DMODEL + q4 * 4);
        }
    };

    issueKM(0); cp_commit();
    issueV(0);  cp_commit();

#pragma unroll
    for (int it = 0; it < 8; ++it) {
        int idx = tid + it * 256;
        int row = idx >> 4, q4 = idx & 15;
        float4 v = *(const float4*)(Qg + baseQ + (size_t)row * DMODEL + q4 * 4);
        *(float4*)&Q_s[row * QK_LD + q4 * 4] = v;
    }
    if (tid < 128) { mrow[tid] = -3.0e38f; lrow[tid] = 0.f; }

    float o[4][2][4];
#pragma unroll
    for (int mi = 0; mi < 4; mi++)
#pragma unroll
        for (int ni = 0; ni < 2; ni++)
#pragma unroll
            for (int j = 0; j < 4; j++) o[mi][ni][j] = 0.f;

    const float INV    = 0.04419417382415922f;   // 1/sqrt(512)
    const float MASKED = -1e10f * 0.04419417382415922f;

    for (int kt = 0; kt < 16; ++kt) {
        cp_wait<1>();
        __syncthreads();   // A

        float s[4][4][4];
#pragma unroll
        for (int mi = 0; mi < 4; mi++)
#pragma unroll
            for (int ni = 0; ni < 4; ni++)
#pragma unroll
                for (int j = 0; j < 4; j++) s[mi][ni][j] = 0.f;

#pragma unroll
        for (int ks = 0; ks < 8; ++ks) {
            int k = ks * 8;
            unsigned a[4][4], b[4][2];
#pragma unroll
            for (int mi = 0; mi < 4; mi++) {
                int rb = wm * 64 + mi * 16;
                a[mi][0] = __float_as_uint(Q_s[(rb + g) * QK_LD + k + l4]);
                a[mi][1] = __float_as_uint(Q_s[(rb + g + 8) * QK_LD + k + l4]);
                a[mi][2] = __float_as_uint(Q_s[(rb + g) * QK_LD + k + l4 + 4]);
                a[mi][3] = __float_as_uint(Q_s[(rb + g + 8) * QK_LD + k + l4 + 4]);
            }
#pragma unroll
            for (int ni = 0; ni < 4; ni++) {
                int nb = wn * 32 + ni * 8;
                b[ni][0] = __float_as_uint(K_s[(nb + g) * QK_LD + k + l4]);
                b[ni][1] = __float_as_uint(K_s[(nb + g) * QK_LD + k + l4 + 4]);
            }
#pragma unroll
            for (int mi = 0; mi < 4; mi++)
#pragma unroll
                for (int ni = 0; ni < 4; ni++)
                    mma_tf32(s[mi][ni], a[mi], b[ni]);
        }

        float m0v[4], m1v[4];
#pragma unroll
        for (int mi = 0; mi < 4; mi++) { m0v[mi] = -3.0e38f; m1v[mi] = -3.0e38f; }
#pragma unroll
        for (int ni = 0; ni < 4; ni++) {
            int c = wn * 32 + ni * 8 + l4 * 2;
            bool z0 = (mkv[c] == 0), z1 = (mkv[c + 1] == 0);
#pragma unroll
            for (int mi = 0; mi < 4; mi++) {
                s[mi][ni][0] = z0 ? MASKED : s[mi][ni][0] * INV;
                s[mi][ni][1] = z1 ? MASKED : s[mi][ni][1] * INV;
                s[mi][ni][2] = z0 ? MASKED : s[mi][ni][2] * INV;
                s[mi][ni][3] = z1 ? MASKED : s[mi][ni][3] * INV;
                m0v[mi] = fmaxf(m0v[mi], fmaxf(s[mi][ni][0], s[mi][ni][1]));
                m1v[mi] = fmaxf(m1v[mi], fmaxf(s[mi][ni][2], s[mi][ni][3]));
            }
        }
#pragma unroll
        for (int mi = 0; mi < 4; mi++) {
            m0v[mi] = fmaxf(m0v[mi], __shfl_xor_sync(0xffffffffu, m0v[mi], 1));
            m0v[mi] = fmaxf(m0v[mi], __shfl_xor_sync(0xffffffffu, m0v[mi], 2));
            m1v[mi] = fmaxf(m1v[mi], __shfl_xor_sync(0xffffffffu, m1v[mi], 1));
            m1v[mi] = fmaxf(m1v[mi], __shfl_xor_sync(0xffffffffu, m1v[mi], 2));
            if (l4 == 0) {
                int r0 = wm * 64 + mi * 16 + g;
                red[r0 * 4 + wn] = m0v[mi];
                red[(r0 + 8) * 4 + wn] = m1v[mi];
            }
        }
        __syncthreads();   // B

        if (kt < 15) { issueKM(kt + 1); cp_commit(); }

        if (tid < 128) {
            float mo = mrow[tid];
            float mx = fmaxf(fmaxf(red[tid * 4 + 0], red[tid * 4 + 1]),
                             fmaxf(red[tid * 4 + 2], red[tid * 4 + 3]));
            mx = fmaxf(mo, mx);
            crow[tid] = __expf(mo - mx);
            mrow[tid] = mx;
        }
        __syncthreads();   // C

#pragma unroll
        for (int mi = 0; mi < 4; mi++) {
            int r0 = wm * 64 + mi * 16 + g;
            int r1 = r0 + 8;
            float mr0 = mrow[r0], mr1 = mrow[r1];
            float ps0 = 0.f, ps1 = 0.f;
#pragma unroll
            for (int ni = 0; ni < 4; ni++) {
                int c = wn * 32 + ni * 8 + l4 * 2;
                float p00 = __expf(s[mi][ni][0] - mr0);
                float p01 = __expf(s[mi][ni][1] - mr0);
                float p10 = __expf(s[mi][ni][2] - mr1);
                float p11 = __expf(s[mi][ni][3] - mr1);
                ps0 += p00 + p01;
                ps1 += p10 + p11;
                P_s[r0 * P_LD + c]     = f2tf32f(p00);
                P_s[r0 * P_LD + c + 1] = f2tf32f(p01);
                P_s[r1 * P_LD + c]     = f2tf32f(p10);
                P_s[r1 * P_LD + c + 1] = f2tf32f(p11);
            }
            ps0 += __shfl_xor_sync(0xffffffffu, ps0, 1);
            ps0 += __shfl_xor_sync(0xffffffffu, ps0, 2);
            ps1 += __shfl_xor_sync(0xffffffffu, ps1, 1);
            ps1 += __shfl_xor_sync(0xffffffffu, ps1, 2);
            if (l4 == 0) {
                red[r0 * 4 + wn] = ps0;
                red[r1 * 4 + wn] = ps1;
            }
            float c0 = crow[r0], c1 = crow[r1];
#pragma unroll
            for (int ni = 0; ni < 2; ni++) {
                o[mi][ni][0] *= c0; o[mi][ni][1] *= c0;
                o[mi][ni][2] *= c1; o[mi][ni][3] *= c1;
            }
        }

        if (kt < 15) cp_wait<1>(); else cp_wait<0>();
        __syncthreads();   // D

        if (tid < 128) {
            float s2 = red[tid * 4 + 0] + red[tid * 4 + 1] + red[tid * 4 + 2] + red[tid * 4 + 3];
            lrow[tid] = lrow[tid] * crow[tid] + s2;
        }

#pragma unroll
        for (int ks = 0; ks < 16; ++ks) {
            int k = ks * 8;
            unsigned a[4][4], b[2][2];
#pragma unroll
            for (int mi = 0; mi < 4; mi++) {
                int rb = wm * 64 + mi * 16;
                a[mi][0] = __float_as_uint(P_s[(rb + g) * P_LD + k + l4]);
                a[mi][1] = __float_as_uint(P_s[(rb + g + 8) * P_LD + k + l4]);
                a[mi][2] = __float_as_uint(P_s[(rb + g) * P_LD + k + l4 + 4]);
                a[mi][3] = __float_as_uint(P_s[(rb + g + 8) * P_LD + k + l4 + 4]);
            }
#pragma unroll
            for (int ni = 0; ni < 2; ni++) {
                int cb = wn * 16 + ni * 8;
                b[ni][0] = __float_as_uint(V_s[(k + l4) * V_LD + cb + g]);
                b[ni][1] = __float_as_uint(V_s[(k + l4 + 4) * V_LD + cb + g]);
            }
#pragma unroll
            for (int mi = 0; mi < 4; mi++)
#pragma unroll
                for (int ni = 0; ni < 2; ni++)
                    mma_tf32(o[mi][ni], a[mi], b[ni]);
        }
        __syncthreads();   // E

        if (kt < 15) { issueV(kt + 1); cp_commit(); }
    }

#pragma unroll
    for (int mi = 0; mi < 4; mi++) {
        int r0 = wm * 64 + mi * 16 + g;
        int r1 = r0 + 8;
        float li0 = 1.f / lrow[r0];
        float li1 = 1.f / lrow[r1];
#pragma unroll
        for (int ni = 0; ni < 2; ni++) {
            int c = wn * 16 + ni * 8 + l4 * 2;
            float2 v0 = {f2tf32f(o[mi][ni][0] * li0), f2tf32f(o[mi][ni][1] * li0)};
            float2 v1 = {f2tf32f(o[mi][ni][2] * li1), f2tf32f(o[mi][ni][3] * li1)};
            *(float2*)(Og + baseQ + (size_t)r0 * DMODEL + c) = v0;
            *(float2*)(Og + baseQ + (size_t)r1 * DMODEL + c) = v1;
        }
    }
}

// ---------------- pipelined tf32 GEMM (R12 config): 128x128x32, 3-stage ----------------
#define G_LD 36
#define G_STG (128 * G_LD)

__device__ __forceinline__ void load_frags(
    const float* __restrict__ As, const float* __restrict__ Bs, int k,
    int wm, int wn, int g, int l4,
    unsigned a[4][4], unsigned b[4][2])
{
#pragma unroll
    for (int mi = 0; mi < 4; mi++) {
        int rb = wm * 64 + mi * 16;
        a[mi][0] = __float_as_uint(As[(rb + g) * G_LD + k + l4]);
        a[mi][1] = __float_as_uint(As[(rb + g + 8) * G_LD + k + l4]);
        a[mi][2] = __float_as_uint(As[(rb + g) * G_LD + k + l4 + 4]);
        a[mi][3] = __float_as_uint(As[(rb + g + 8) * G_LD + k + l4 + 4]);
    }
#pragma unroll
    for (int ni = 0; ni < 4; ni++) {
        int nb = wn * 32 + ni * 8;
        b[ni][0] = __float_as_uint(Bs[(nb + g) * G_LD + k + l4]);
        b[ni][1] = __float_as_uint(Bs[(nb + g) * G_LD + k + l4 + 4]);
    }
}

template <bool RELU, bool ROUND_OUT>
__global__ __launch_bounds__(256) void sgemm_tf32_pipe(
    const float* __restrict__ A, const float* __restrict__ B,
    const float* __restrict__ bias, float* __restrict__ C,
    int M, int N, int K)
{
    extern __shared__ float smem[];
    int tid = threadIdx.x;
    int warp = tid >> 5, lane = tid & 31;
    int g = lane >> 2, l4 = lane & 3;
    int wm = warp >> 2, wn = warp & 3;
    int n0 = blockIdx.x * 128, m0 = blockIdx.y * 128;

    int crow = tid >> 3;
    int ccol = (tid & 7) * 4;

    const float* Abase = A + (size_t)m0 * K;
    const float* Bbase = B + (size_t)n0 * K;

    auto issue = [&](int s, int kb) {
        float* As = smem + s * 2 * G_STG;
        float* Bs = As + G_STG;
#pragma unroll
        for (int it = 0; it < 4; ++it) {
            int row = crow + it * 32;
            uint32_t da = (uint32_t)__cvta_generic_to_shared(&As[row * G_LD + ccol]);
            cp_async16(da, Abase + (size_t)row * K + kb + ccol);
            uint32_t db = (uint32_t)__cvta_generic_to_shared(&Bs[row * G_LD + ccol]);
            cp_async16(db, Bbase + (size_t)row * K + kb + ccol);
        }
    };

    float acc[4][4][4];
#pragma unroll
    for (int mi = 0; mi < 4; mi++)
#pragma unroll
        for (int ni = 0; ni < 4; ni++)
#pragma unroll
            for (int j = 0; j < 4; j++) acc[mi][ni][j] = 0.f;

    int nt = K >> 5;
    issue(0, 0);  cp_commit();
    issue(1, 32); cp_commit();
    cp_wait<1>();
    __syncthreads();

    for (int t = 0; t < nt; ++t) {
        int st = t % 3;
        if (t + 2 < nt) { issue((t + 2) % 3, (t + 2) * 32); cp_commit(); }

        const float* As = smem + st * 2 * G_STG;
        const float* Bs = As + G_STG;

        unsigned afr[2][4][4], bfr[2][4][2];
        load_frags(As, Bs, 0, wm, wn, g, l4, afr[0], bfr[0]);
#pragma unroll
        for (int ks = 0; ks < 4; ++ks) {
            if (ks < 3)
                load_frags(As, Bs, (ks + 1) * 8, wm, wn, g, l4,
                           afr[(ks + 1) & 1], bfr[(ks + 1) & 1]);
#pragma unroll
            for (int mi = 0; mi < 4; mi++)
#pragma unroll
                for (int ni = 0; ni < 4; ni++)
                    mma_tf32(acc[mi][ni], afr[ks & 1][mi], bfr[ks & 1][ni]);
        }

        if (t + 2 < nt) cp_wait<1>();
        else            cp_wait<0>();
        __syncthreads();
    }

#pragma unroll
    for (int ni = 0; ni < 4; ni++) {
        int c = n0 + wn * 32 + ni * 8 + l4 * 2;
        float b0 = bias[c], b1 = bias[c + 1];
#pragma unroll
        for (int mi = 0; mi < 4; mi++) {
            int r0 = m0 + wm * 64 + mi * 16 + g;
            int r1 = r0 + 8;
            float2 v0 = {acc[mi][ni][0] + b0, acc[mi][ni][1] + b1};
            float2 v1 = {acc[mi][ni][2] + b0, acc[mi][ni][3] + b1};
            if (RELU) {
                v0.x = fmaxf(v0.x, 0.f); v0.y = fmaxf(v0.y, 0.f);
                v1.x = fmaxf(v1.x, 0.f); v1.y = fmaxf(v1.y, 0.f);
            }
            if (ROUND_OUT) {
                v0.x = f2tf32f(v0.x); v0.y = f2tf32f(v0.y);
                v1.x = f2tf32f(v1.x); v1.y = f2tf32f(v1.y);
            }
            *(float2*)(C + (size_t)r0 * N + c) = v0;
            *(float2*)(C + (size_t)r1 * N + c) = v1;
        }
    }
}

// ---------------- warp-per-token residual-add + LayerNorm (+ optional tf32 copy) ----------------
__global__ __launch_bounds__(256) void add_ln_kernel(
    const float* __restrict__ x, const float* __restrict__ a,
    const float* __restrict__ g, const float* __restrict__ b,
    float* __restrict__ dst, float* __restrict__ dst_tf)
{
    int warp = threadIdx.x >> 5, lane = threadIdx.x & 31;
    size_t t = (size_t)blockIdx.x * 8 + warp;

    const float4* xp = (const float4*)(x + t * DMODEL);
    const float4* ap = (const float4*)(a + t * DMODEL);
    float4 v[4];
    float s = 0.f, sq = 0.f;
#pragma unroll
    for (int i = 0; i < 4; i++) {
        float4 xv = xp[lane + 32 * i];
        float4 av = ap[lane + 32 * i];
        xv.x += av.x; xv.y += av.y; xv.z += av.z; xv.w += av.w;
        v[i] = xv;
        s  += xv.x + xv.y + xv.z + xv.w;
        sq += xv.x * xv.x + xv.y * xv.y + xv.z * xv.z + xv.w * xv.w;
    }
#pragma unroll
    for (int o = 16; o > 0; o >>= 1) {
        s  += __shfl_xor_sync(0xffffffffu, s,  o);
        sq += __shfl_xor_sync(0xffffffffu, sq, o);
    }
    float mean = s * (1.f / 512.f);
    float var  = sq * (1.f / 512.f) - mean * mean;
    float rs = rsqrtf(var + 1e-5f);

    float4* dp = (float4*)(dst + t * DMODEL);
    float4* dtp = dst_tf ? (float4*)(dst_tf + t * DMODEL) : (float4*)0;
#pragma unroll
    for (int i = 0; i < 4; i++) {
        float4 gg  = ((const float4*)g)[lane + 32 * i];
        float4 bb2 = ((const float4*)b)[lane + 32 * i];
        float4 o4;
        o4.x = (v[i].x - mean) * rs * gg.x + bb2.x;
        o4.y = (v[i].y - mean) * rs * gg.y + bb2.y;
        o4.z = (v[i].z - mean) * rs * gg.z + bb2.z;
        o4.w = (v[i].w - mean) * rs * gg.w + bb2.w;
        dp[lane + 32 * i] = o4;
        if (dtp) {
            float4 r4;
            r4.x = f2tf32f(o4.x); r4.y = f2tf32f(o4.y);
            r4.z = f2tf32f(o4.z); r4.w = f2tf32f(o4.w);
            dtp[lane + 32 * i] = r4;
        }
    }
}

// ---------------- launcher ----------------
extern "C" void kernel_launch(void* const* d_in, const int* in_sizes, int n_in,
                              void* d_out, int out_size)
{
    const int*   src  = (const int*)d_in[0];
    const int*   mask = (const int*)d_in[1];
    const float* emb = (const float*)d_in[2];
    const float* Wq  = (const float*)d_in[3];
    const float* bq  = (const float*)d_in[4];
    const float* Wk  = (const float*)d_in[5];
    const float* bk  = (const float*)d_in[6];
    const float* Wv  = (const float*)d_in[7];
    const float* bv  = (const float*)d_in[8];
    const float* Wo  = (const float*)d_in[9];
    const float* bo  = (const float*)d_in[10];
    const float* W1  = (const float*)d_in[11];
    const float* b1  = (const float*)d_in[12];
    const float* W2  = (const float*)d_in[13];
    const float* b2  = (const float*)d_in[14];
    const float* ln1g = (const float*)d_in[15];
    const float* ln1b = (const float*)d_in[16];
    const float* ln2g = (const float*)d_in[17];
    const float* ln2b = (const float*)d_in[18];
    float* out = (float*)d_out;

    float *h, *htf, *q, *k, *v, *att, *proj, *ff, *woT, *w1T, *w2T, *wqkvT;
    cudaGetSymbolAddress((void**)&h,    g_h);
    cudaGetSymbolAddress((void**)&htf,  g_htf);
    cudaGetSymbolAddress((void**)&q,    g_q);
    cudaGetSymbolAddress((void**)&k,    g_k);
    cudaGetSymbolAddress((void**)&v,    g_v);
    cudaGetSymbolAddress((void**)&att,  g_att);
    cudaGetSymbolAddress((void**)&proj, g_proj);
    cudaGetSymbolAddress((void**)&ff,   g_ff);
    cudaGetSymbolAddress((void**)&woT,  g_wo_t);
    cudaGetSymbolAddress((void**)&w1T,  g_w1_t);
    cudaGetSymbolAddress((void**)&w2T,  g_w2_t);
    cudaGetSymbolAddress((void**)&wqkvT, g_wqkv_t);

    // flash smem: 2*128*68 + 128*72 + 128*132 + 3*128 + 512 + 128 floats = 178,176 B
    const size_t flashSmem = (size_t)(2 * 128 * QK_LD + 128 * V_LD + 128 * P_LD
                                      + 3 * 128 + 512 + 128) * sizeof(float);
    cudaFuncSetAttribute(flash_kernel, cudaFuncAttributeMaxDynamicSharedMemorySize,
                         (int)flashSmem);
    const size_t gemmSmem = (size_t)3 * 2 * G_STG * sizeof(float);   // 110,592 B
    cudaFuncSetAttribute(sgemm_tf32_pipe<false, false>,
                         cudaFuncAttributeMaxDynamicSharedMemorySize, (int)gemmSmem);
    cudaFuncSetAttribute(sgemm_tf32_pipe<true, true>,
                         cudaFuncAttributeMaxDynamicSharedMemorySize, (int)gemmSmem);
    const size_t qkvSmem = (size_t)(128 + 3 * 64) * QKV_LD * sizeof(float);
    cudaFuncSetAttribute(qkv_mma_kernel, cudaFuncAttributeMaxDynamicSharedMemorySize,
                         (int)qkvSmem);

    // pre-round all GEMM weights to tf32
    {
        int n4;
        n4 = NLAYER * DMODEL * DMODEL / 4;
        round_tf32_kernel<<<(n4 + 255) / 256, 256>>>((const float4*)Wo, (float4*)woT, n4);
        n4 = NLAYER * FDIM * DMODEL / 4;
        round_tf32_kernel<<<(n4 + 255) / 256, 256>>>((const float4*)W1, (float4*)w1T, n4);
        round_tf32_kernel<<<(n4 + 255) / 256, 256>>>((const float4*)W2, (float4*)w2T, n4);
        int nq = NLAYER * HDIM * HDIM / 4;
        pack_qkv_weights_kernel<<<(nq + 255) / 256, 256>>>(
            (const float4*)Wq, (const float4*)Wk, (const float4*)Wv, (float4*)wqkvT);
    }

    embed_kernel<<<T_TOK, 128>>>(src, emb, h, htf);

    for (int l = 0; l < NLAYER; ++l) {
        qkv_mma_kernel<<<256, 256, qkvSmem>>>(htf,
            wqkvT + (size_t)l * 3 * HDIM * HDIM,
            bq + l * HDIM, bk + l * HDIM, bv + l * HDIM,
            q, k, v);

        flash_kernel<<<dim3(16, NHEAD, 2), 256, flashSmem>>>(q, k, v, mask, att);

        sgemm_tf32_pipe<false, false><<<dim3(4, 32), 256, gemmSmem>>>(
            att, woT + (size_t)l * DMODEL * DMODEL, bo + l * DMODEL, proj,
            T_TOK, DMODEL, DMODEL);

        add_ln_kernel<<<T_TOK / 8, 256>>>(h, proj, ln1g + l * DMODEL, ln1b + l * DMODEL,
                                          h, htf);

        sgemm_tf32_pipe<true, true><<<dim3(16, 32), 256, gemmSmem>>>(
            htf, w1T + (size_t)l * FDIM * DMODEL, b1 + l * FDIM, ff,
            T_TOK, FDIM, DMODEL);

        sgemm_tf32_pipe<false, false><<<dim3(4, 32), 256, gemmSmem>>>(
            ff, w2T + (size_t)l * DMODEL * FDIM, b2 + l * DMODEL, proj,
            T_TOK, DMODEL, FDIM);

        add_ln_kernel<<<T_TOK / 8, 256>>>(h, proj, ln2g + l * DMODEL, ln2b + l * DMODEL,
                                          (l == NLAYER - 1) ? out : h,
                                          (l == NLAYER - 1) ? (float*)nullptr : htf);
    }
}

// round 17
// speedup vs baseline: 1.0215x; 1.0006x over previous
#include <cuda_runtime.h>
#include <cstdint>
#include <cstddef>

#define T_TOK 4096
#define DMODEL 512
#define NHEAD 8
#define HDIM 64
#define FDIM 2048
#define NLAYER 6
#define SEQ 2048

// ---------------- scratch (static device globals; no allocation) ----------------
__device__ float g_h[T_TOK * DMODEL];
__device__ float g_htf[T_TOK * DMODEL];
__device__ float g_q[T_TOK * DMODEL];
__device__ float g_k[T_TOK * DMODEL];
__device__ float g_v[T_TOK * DMODEL];
__device__ float g_att[T_TOK * DMODEL];
__device__ float g_proj[T_TOK * DMODEL];
__device__ float g_ff[T_TOK * FDIM];
__device__ float g_wo_t[NLAYER * DMODEL * DMODEL];
__device__ float g_w1_t[NLAYER * FDIM * DMODEL];
__device__ float g_w2_t[NLAYER * DMODEL * FDIM];
__device__ float g_wqkv_t[NLAYER * 3 * HDIM * HDIM];

// ---------------- tf32 / cp.async helpers ----------------
__device__ __forceinline__ unsigned f2tf32(float f) {
    unsigned r;
    asm("cvt.rna.tf32.f32 %0, %1;" : "=r"(r) : "f"(f));
    return r;
}
__device__ __forceinline__ float f2tf32f(float f) { return __uint_as_float(f2tf32(f)); }

__device__ __forceinline__ void mma_tf32(float d[4], const unsigned a[4], const unsigned b[2]) {
    asm volatile(
        "mma.sync.aligned.m16n8k8.row.col.f32.tf32.tf32.f32 "
        "{%0,%1,%2,%3}, {%4,%5,%6,%7}, {%8,%9}, {%0,%1,%2,%3};"
        : "+f"(d[0]), "+f"(d[1]), "+f"(d[2]), "+f"(d[3])
        : "r"(a[0]), "r"(a[1]), "r"(a[2]), "r"(a[3]), "r"(b[0]), "r"(b[1]));
}

__device__ __forceinline__ void cp_async16(uint32_t dst, const void* src) {
    asm volatile("cp.async.ca.shared.global [%0], [%1], 16;" :: "r"(dst), "l"(src));
}
__device__ __forceinline__ void cp_commit() {
    asm volatile("cp.async.commit_group;");
}
template <int N>
__device__ __forceinline__ void cp_wait() {
    asm volatile("cp.async.wait_group %0;" :: "n"(N));
}

// ---------------- weight rounding (fp32 -> tf32 bits) ----------------
__global__ __launch_bounds__(256) void round_tf32_kernel(
    const float4* __restrict__ x, float4* __restrict__ y, int n4)
{
    int i = blockIdx.x * 256 + threadIdx.x;
    if (i < n4) {
        float4 v = x[i];
        v.x = f2tf32f(v.x); v.y = f2tf32f(v.y);
        v.z = f2tf32f(v.z); v.w = f2tf32f(v.w);
        y[i] = v;
    }
}

__global__ __launch_bounds__(256) void pack_qkv_weights_kernel(
    const float4* __restrict__ Wq, const float4* __restrict__ Wk,
    const float4* __restrict__ Wv, float4* __restrict__ dst)
{
    int i = blockIdx.x * 256 + threadIdx.x;
    int per = NLAYER * HDIM * HDIM / 4;
    if (i < per) {
        int l = i / (HDIM * HDIM / 4);
        int r = i % (HDIM * HDIM / 4);
        float4 vq = Wq[i], vk = Wk[i], vv = Wv[i];
        vq.x = f2tf32f(vq.x); vq.y = f2tf32f(vq.y); vq.z = f2tf32f(vq.z); vq.w = f2tf32f(vq.w);
        vk.x = f2tf32f(vk.x); vk.y = f2tf32f(vk.y); vk.z = f2tf32f(vk.z); vk.w = f2tf32f(vk.w);
        vv.x = f2tf32f(vv.x); vv.y = f2tf32f(vv.y); vv.z = f2tf32f(vv.z); vv.w = f2tf32f(vv.w);
        int base = l * 3 * (HDIM * HDIM / 4);
        dst[base + r] = vq;
        dst[base + (HDIM * HDIM / 4) + r] = vk;
        dst[base + 2 * (HDIM * HDIM / 4) + r] = vv;
    }
}

// ---------------- embedding (writes h and tf32-rounded htf) ----------------
__global__ __launch_bounds__(128) void embed_kernel(
    const int* __restrict__ src, const float* __restrict__ emb,
    float* __restrict__ h, float* __restrict__ htf)
{
    int t = blockIdx.x;
    int tok = src[t];
    const float4* e = (const float4*)(emb + (size_t)tok * DMODEL);
    const float s = 22.627416997969522f;  // sqrt(512)
    float4 v = e[threadIdx.x];
    v.x *= s; v.y *= s; v.z *= s; v.w *= s;
    ((float4*)(h + (size_t)t * DMODEL))[threadIdx.x] = v;
    float4 r;
    r.x = f2tf32f(v.x); r.y = f2tf32f(v.y);
    r.z = f2tf32f(v.z); r.w = f2tf32f(v.w);
    ((float4*)(htf + (size_t)t * DMODEL))[threadIdx.x] = r;
}

// ---------------- QKV via tf32 MMA (R12 proven) ----------------
#define QKV_LD 68

__global__ __launch_bounds__(256, 2) void qkv_mma_kernel(
    const float* __restrict__ A,
    const float* __restrict__ Wt,
    const float* __restrict__ bq, const float* __restrict__ bk, const float* __restrict__ bv,
    float* __restrict__ Q, float* __restrict__ K, float* __restrict__ V)
{
    extern __shared__ float sm[];
    float* A_s = sm;                       // [128][68]
    float* W_s = A_s + 128 * QKV_LD;       // [3][64][68]

    int tid = threadIdx.x;
    int warp = tid >> 5, lane = tid & 31;
    int g = lane >> 2, l4 = lane & 3;
    int wm = warp >> 1, wn = warp & 1;
    size_t r0 = (size_t)blockIdx.x * 128;

#pragma unroll
    for (int it = 0; it < 8; ++it) {
        int idx = tid + it * 256;
        int row = idx >> 4, q4 = idx & 15;
        uint32_t da = (uint32_t)__cvta_generic_to_shared(&A_s[row * QKV_LD + q4 * 4]);
        cp_async16(da, A + (r0 + row) * HDIM + q4 * 4);
    }
#pragma unroll
    for (int it = 0; it < 12; ++it) {
        int idx = tid + it * 256;
        int m = idx >> 10;
        int rem = idx & 1023;
        int row = rem >> 4, q4 = rem & 15;
        uint32_t dw = (uint32_t)__cvta_generic_to_shared(
            &W_s[m * 64 * QKV_LD + row * QKV_LD + q4 * 4]);
        cp_async16(dw, Wt + m * HDIM * HDIM + row * HDIM + q4 * 4);
    }
    cp_commit();
    cp_wait<0>();
    __syncthreads();

#pragma unroll
    for (int m = 0; m < 3; ++m) {
        const float* Ws = W_s + m * 64 * QKV_LD;
        float acc[2][4][4];
#pragma unroll
        for (int mi = 0; mi < 2; mi++)
#pragma unroll
            for (int ni = 0; ni < 4; ni++)
#pragma unroll
                for (int j = 0; j < 4; j++) acc[mi][ni][j] = 0.f;

#pragma unroll
        for (int ks = 0; ks < 8; ++ks) {
            int k = ks * 8;
            unsigned a[2][4], b[4][2];
#pragma unroll
            for (int mi = 0; mi < 2; mi++) {
                int rb = wm * 32 + mi * 16;
                a[mi][0] = __float_as_uint(A_s[(rb + g) * QKV_LD + k + l4]);
                a[mi][1] = __float_as_uint(A_s[(rb + g + 8) * QKV_LD + k + l4]);
                a[mi][2] = __float_as_uint(A_s[(rb + g) * QKV_LD + k + l4 + 4]);
                a[mi][3] = __float_as_uint(A_s[(rb + g + 8) * QKV_LD + k + l4 + 4]);
            }
#pragma unroll
            for (int ni = 0; ni < 4; ni++) {
                int nb = wn * 32 + ni * 8;
                b[ni][0] = __float_as_uint(Ws[(nb + g) * QKV_LD + k + l4]);
                b[ni][1] = __float_as_uint(Ws[(nb + g) * QKV_LD + k + l4 + 4]);
            }
#pragma unroll
            for (int mi = 0; mi < 2; mi++)
#pragma unroll
                for (int ni = 0; ni < 4; ni++)
                    mma_tf32(acc[mi][ni], a[mi], b[ni]);
        }

        const float* bias = (m == 0) ? bq : ((m == 1) ? bk : bv);
        float* outp = (m == 0) ? Q : ((m == 1) ? K : V);
#pragma unroll
        for (int ni = 0; ni < 4; ni++) {
            int c = wn * 32 + ni * 8 + l4 * 2;
            float b0 = bias[c], b1 = bias[c + 1];
#pragma unroll
            for (int mi = 0; mi < 2; mi++) {
                size_t rr0 = r0 + wm * 32 + mi * 16 + g;
                size_t rr1 = rr0 + 8;
                float2 v0 = {f2tf32f(acc[mi][ni][0] + b0), f2tf32f(acc[mi][ni][1] + b1)};
                float2 v1 = {f2tf32f(acc[mi][ni][2] + b0), f2tf32f(acc[mi][ni][3] + b1)};
                *(float2*)(outp + rr0 * HDIM + c) = v0;
                *(float2*)(outp + rr1 * HDIM + c) = v1;
            }
        }
    }
}

// ---------------- flash attention (R14 structure; float2 P stores) ----------------
#define QK_LD 68
#define V_LD 72
#define P_LD 132

__global__ __launch_bounds__(256) void flash_kernel(
    const float* __restrict__ Qg, const float* __restrict__ Kg,
    const float* __restrict__ Vg, const int* __restrict__ mask,
    float* __restrict__ Og)
{
    extern __shared__ float sm[];
    float* Q_s  = sm;                     // [128][68]
    float* K_s  = Q_s + 128 * QK_LD;      // [128][68]
    float* V_s  = K_s + 128 * QK_LD;      // [128][72]
    float* P_s  = V_s + 128 * V_LD;       // [128][132]
    float* mrow = P_s + 128 * P_LD;
    float* crow = mrow + 128;
    float* lrow = crow + 128;
    float* red  = lrow + 128;             // [128][4]
    int*   mkv  = (int*)(red + 512);      // [128]

    int tid = threadIdx.x;
    int warp = tid >> 5, lane = tid & 31;
    int g = lane >> 2, l4 = lane & 3;
    int wm = warp >> 2, wn = warp & 3;

    int qt = blockIdx.x, hh = blockIdx.y, n = blockIdx.z;
    int q0 = qt * 128;
    size_t baseQ  = ((size_t)(n * SEQ + q0)) * DMODEL + hh * HDIM;
    size_t baseKV = ((size_t)(n * SEQ)) * DMODEL + hh * HDIM;
    const int* maskbase = mask + n * SEQ;

    auto issueKM = [&](int kt) {
        size_t bK = baseKV + (size_t)(kt * 128) * DMODEL;
#pragma unroll
        for (int it = 0; it < 8; ++it) {
            int idx = tid + it * 256;
            int row = idx >> 4, q4 = idx & 15;
            uint32_t dk = (uint32_t)__cvta_generic_to_shared(&K_s[row * QK_LD + q4 * 4]);
            cp_async16(dk, Kg + bK + (size_t)row * DMODEL + q4 * 4);
        }
        if (tid < 32) {
            uint32_t dm = (uint32_t)__cvta_generic_to_shared(&mkv[tid * 4]);
            cp_async16(dm, maskbase + kt * 128 + tid * 4);
        }
    };
    auto issueV = [&](int kt) {
        size_t bK = baseKV + (size_t)(kt * 128) * DMODEL;
#pragma unroll
        for (int it = 0; it < 8; ++it) {
            int idx = tid + it * 256;
            int row = idx >> 4, q4 = idx & 15;
            uint32_t dv = (uint32_t)__cvta_generic_to_shared(&V_s[row * V_LD + q4 * 4]);
            cp_async16(dv, Vg + bK + (size_t)row * DMODEL + q4 * 4);
        }
    };

    issueKM(0); cp_commit();
    issueV(0);  cp_commit();

#pragma unroll
    for (int it = 0; it < 8; ++it) {
        int idx = tid + it * 256;
        int row = idx >> 4, q4 = idx & 15;
        float4 v = *(const float4*)(Qg + baseQ + (size_t)row * DMODEL + q4 * 4);
        *(float4*)&Q_s[row * QK_LD + q4 * 4] = v;
    }
    if (tid < 128) { mrow[tid] = -3.0e38f; lrow[tid] = 0.f; }

    float o[4][2][4];
#pragma unroll
    for (int mi = 0; mi < 4; mi++)
#pragma unroll
        for (int ni = 0; ni < 2; ni++)
#pragma unroll
            for (int j = 0; j < 4; j++) o[mi][ni][j] = 0.f;

    const float INV    = 0.04419417382415922f;   // 1/sqrt(512)
    const float MASKED = -1e10f * 0.04419417382415922f;

    for (int kt = 0; kt < 16; ++kt) {
        cp_wait<1>();
        __syncthreads();   // A

        float s[4][4][4];
#pragma unroll
        for (int mi = 0; mi < 4; mi++)
#pragma unroll
            for (int ni = 0; ni < 4; ni++)
#pragma unroll
                for (int j = 0; j < 4; j++) s[mi][ni][j] = 0.f;

#pragma unroll
        for (int ks = 0; ks < 8; ++ks) {
            int k = ks * 8;
            unsigned a[4][4], b[4][2];
#pragma unroll
            for (int mi = 0; mi < 4; mi++) {
                int rb = wm * 64 + mi * 16;
                a[mi][0] = __float_as_uint(Q_s[(rb + g) * QK_LD + k + l4]);
                a[mi][1] = __float_as_uint(Q_s[(rb + g + 8) * QK_LD + k + l4]);
                a[mi][2] = __float_as_uint(Q_s[(rb + g) * QK_LD + k + l4 + 4]);
                a[mi][3] = __float_as_uint(Q_s[(rb + g + 8) * QK_LD + k + l4 + 4]);
            }
#pragma unroll
            for (int ni = 0; ni < 4; ni++) {
                int nb = wn * 32 + ni * 8;
                b[ni][0] = __float_as_uint(K_s[(nb + g) * QK_LD + k + l4]);
                b[ni][1] = __float_as_uint(K_s[(nb + g) * QK_LD + k + l4 + 4]);
            }
#pragma unroll
            for (int mi = 0; mi < 4; mi++)
#pragma unroll
                for (int ni = 0; ni < 4; ni++)
                    mma_tf32(s[mi][ni], a[mi], b[ni]);
        }

        float m0v[4], m1v[4];
#pragma unroll
        for (int mi = 0; mi < 4; mi++) { m0v[mi] = -3.0e38f; m1v[mi] = -3.0e38f; }
#pragma unroll
        for (int ni = 0; ni < 4; ni++) {
            int c = wn * 32 + ni * 8 + l4 * 2;
            bool z0 = (mkv[c] == 0), z1 = (mkv[c + 1] == 0);
#pragma unroll
            for (int mi = 0; mi < 4; mi++) {
                s[mi][ni][0] = z0 ? MASKED : s[mi][ni][0] * INV;
                s[mi][ni][1] = z1 ? MASKED : s[mi][ni][1] * INV;
                s[mi][ni][2] = z0 ? MASKED : s[mi][ni][2] * INV;
                s[mi][ni][3] = z1 ? MASKED : s[mi][ni][3] * INV;
                m0v[mi] = fmaxf(m0v[mi], fmaxf(s[mi][ni][0], s[mi][ni][1]));
                m1v[mi] = fmaxf(m1v[mi], fmaxf(s[mi][ni][2], s[mi][ni][3]));
            }
        }
#pragma unroll
        for (int mi = 0; mi < 4; mi++) {
            m0v[mi] = fmaxf(m0v[mi], __shfl_xor_sync(0xffffffffu, m0v[mi], 1));
            m0v[mi] = fmaxf(m0v[mi], __shfl_xor_sync(0xffffffffu, m0v[mi], 2));
            m1v[mi] = fmaxf(m1v[mi], __shfl_xor_sync(0xffffffffu, m1v[mi], 1));
            m1v[mi] = fmaxf(m1v[mi], __shfl_xor_sync(0xffffffffu, m1v[mi], 2));
            if (l4 == 0) {
                int r0 = wm * 64 + mi * 16 + g;
                red[r0 * 4 + wn] = m0v[mi];
                red[(r0 + 8) * 4 + wn] = m1v[mi];
            }
        }
        __syncthreads();   // B

        if (kt < 15) { issueKM(kt + 1); cp_commit(); }

        if (tid < 128) {
            float mo = mrow[tid];
            float mx = fmaxf(fmaxf(red[tid * 4 + 0], red[tid * 4 + 1]),
                             fmaxf(red[tid * 4 + 2], red[tid * 4 + 3]));
            mx = fmaxf(mo, mx);
            crow[tid] = __expf(mo - mx);
            mrow[tid] = mx;
        }
        __syncthreads();   // C

#pragma unroll
        for (int mi = 0; mi < 4; mi++) {
            int r0 = wm * 64 + mi * 16 + g;
            int r1 = r0 + 8;
            float mr0 = mrow[r0], mr1 = mrow[r1];
            float ps0 = 0.f, ps1 = 0.f;
#pragma unroll
            for (int ni = 0; ni < 4; ni++) {
                int c = wn * 32 + ni * 8 + l4 * 2;
                float p00 = __expf(s[mi][ni][0] - mr0);
                float p01 = __expf(s[mi][ni][1] - mr0);
                float p10 = __expf(s[mi][ni][2] - mr1);
                float p11 = __expf(s[mi][ni][3] - mr1);
                ps0 += p00 + p01;
                ps1 += p10 + p11;
                float2 w0 = {f2tf32f(p00), f2tf32f(p01)};
                float2 w1 = {f2tf32f(p10), f2tf32f(p11)};
                *(float2*)&P_s[r0 * P_LD + c] = w0;
                *(float2*)&P_s[r1 * P_LD + c] = w1;
            }
            ps0 += __shfl_xor_sync(0xffffffffu, ps0, 1);
            ps0 += __shfl_xor_sync(0xffffffffu, ps0, 2);
            ps1 += __shfl_xor_sync(0xffffffffu, ps1, 1);
            ps1 += __shfl_xor_sync(0xffffffffu, ps1, 2);
            if (l4 == 0) {
                red[r0 * 4 + wn] = ps0;
                red[r1 * 4 + wn] = ps1;
            }
            float c0 = crow[r0], c1 = crow[r1];
#pragma unroll
            for (int ni = 0; ni < 2; ni++) {
                o[mi][ni][0] *= c0; o[mi][ni][1] *= c0;
                o[mi][ni][2] *= c1; o[mi][ni][3] *= c1;
            }
        }

        if (kt < 15) cp_wait<1>(); else cp_wait<0>();
        __syncthreads();   // D

        if (tid < 128) {
            float s2 = red[tid * 4 + 0] + red[tid * 4 + 1] + red[tid * 4 + 2] + red[tid * 4 + 3];
            lrow[tid] = lrow[tid] * crow[tid] + s2;
        }

#pragma unroll
        for (int ks = 0; ks < 16; ++ks) {
            int k = ks * 8;
            unsigned a[4][4], b[2][2];
#pragma unroll
            for (int mi = 0; mi < 4; mi++) {
                int rb = wm * 64 + mi * 16;
                a[mi][0] = __float_as_uint(P_s[(rb + g) * P_LD + k + l4]);
                a[mi][1] = __float_as_uint(P_s[(rb + g + 8) * P_LD + k + l4]);
                a[mi][2] = __float_as_uint(P_s[(rb + g) * P_LD + k + l4 + 4]);
                a[mi][3] = __float_as_uint(P_s[(rb + g + 8) * P_LD + k + l4 + 4]);
            }
#pragma unroll
            for (int ni = 0; ni < 2; ni++) {
                int cb = wn * 16 + ni * 8;
                b[ni][0] = __float_as_uint(V_s[(k + l4) * V_LD + cb + g]);
                b[ni][1] = __float_as_uint(V_s[(k + l4 + 4) * V_LD + cb + g]);
            }
#pragma unroll
            for (int mi = 0; mi < 4; mi++)
#pragma unroll
                for (int ni = 0; ni < 2; ni++)
                    mma_tf32(o[mi][ni], a[mi], b[ni]);
        }
        __syncthreads();   // E

        if (kt < 15) { issueV(kt + 1); cp_commit(); }
    }

#pragma unroll
    for (int mi = 0; mi < 4; mi++) {
        int r0 = wm * 64 + mi * 16 + g;
        int r1 = r0 + 8;
        float li0 = 1.f / lrow[r0];
        float li1 = 1.f / lrow[r1];
#pragma unroll
        for (int ni = 0; ni < 2; ni++) {
            int c = wn * 16 + ni * 8 + l4 * 2;
            float2 v0 = {f2tf32f(o[mi][ni][0] * li0), f2tf32f(o[mi][ni][1] * li0)};
            float2 v1 = {f2tf32f(o[mi][ni][2] * li1), f2tf32f(o[mi][ni][3] * li1)};
            *(float2*)(Og + baseQ + (size_t)r0 * DMODEL + c) = v0;
            *(float2*)(Og + baseQ + (size_t)r1 * DMODEL + c) = v1;
        }
    }
}

// ---------------- pipelined tf32 GEMM (R12 config): 128x128x32, 3-stage ----------------
#define G_LD 36
#define G_STG (128 * G_LD)

__device__ __forceinline__ void load_frags(
    const float* __restrict__ As, const float* __restrict__ Bs, int k,
    int wm, int wn, int g, int l4,
    unsigned a[4][4], unsigned b[4][2])
{
#pragma unroll
    for (int mi = 0; mi < 4; mi++) {
        int rb = wm * 64 + mi * 16;
        a[mi][0] = __float_as_uint(As[(rb + g) * G_LD + k + l4]);
        a[mi][1] = __float_as_uint(As[(rb + g + 8) * G_LD + k + l4]);
        a[mi][2] = __float_as_uint(As[(rb + g) * G_LD + k + l4 + 4]);
        a[mi][3] = __float_as_uint(As[(rb + g + 8) * G_LD + k + l4 + 4]);
    }
#pragma unroll
    for (int ni = 0; ni < 4; ni++) {
        int nb = wn * 32 + ni * 8;
        b[ni][0] = __float_as_uint(Bs[(nb + g) * G_LD + k + l4]);
        b[ni][1] = __float_as_uint(Bs[(nb + g) * G_LD + k + l4 + 4]);
    }
}

template <bool RELU, bool ROUND_OUT>
__global__ __launch_bounds__(256) void sgemm_tf32_pipe(
    const float* __restrict__ A, const float* __restrict__ B,
    const float* __restrict__ bias, float* __restrict__ C,
    int M, int N, int K)
{
    extern __shared__ float smem[];
    int tid = threadIdx.x;
    int warp = tid >> 5, lane = tid & 31;
    int g = lane >> 2, l4 = lane & 3;
    int wm = warp >> 2, wn = warp & 3;
    int n0 = blockIdx.x * 128, m0 = blockIdx.y * 128;

    int crow = tid >> 3;
    int ccol = (tid & 7) * 4;

    const float* Abase = A + (size_t)m0 * K;
    const float* Bbase = B + (size_t)n0 * K;

    auto issue = [&](int s, int kb) {
        float* As = smem + s * 2 * G_STG;
        float* Bs = As + G_STG;
#pragma unroll
        for (int it = 0; it < 4; ++it) {
            int row = crow + it * 32;
            uint32_t da = (uint32_t)__cvta_generic_to_shared(&As[row * G_LD + ccol]);
            cp_async16(da, Abase + (size_t)row * K + kb + ccol);
            uint32_t db = (uint32_t)__cvta_generic_to_shared(&Bs[row * G_LD + ccol]);
            cp_async16(db, Bbase + (size_t)row * K + kb + ccol);
        }
    };

    float acc[4][4][4];
#pragma unroll
    for (int mi = 0; mi < 4; mi++)
#pragma unroll
        for (int ni = 0; ni < 4; ni++)
#pragma unroll
            for (int j = 0; j < 4; j++) acc[mi][ni][j] = 0.f;

    int nt = K >> 5;
    issue(0, 0);  cp_commit();
    issue(1, 32); cp_commit();
    cp_wait<1>();
    __syncthreads();

    for (int t = 0; t < nt; ++t) {
        int st = t % 3;
        if (t + 2 < nt) { issue((t + 2) % 3, (t + 2) * 32); cp_commit(); }

        const float* As = smem + st * 2 * G_STG;
        const float* Bs = As + G_STG;

        unsigned afr[2][4][4], bfr[2][4][2];
        load_frags(As, Bs, 0, wm, wn, g, l4, afr[0], bfr[0]);
#pragma unroll
        for (int ks = 0; ks < 4; ++ks) {
            if (ks < 3)
                load_frags(As, Bs, (ks + 1) * 8, wm, wn, g, l4,
                           afr[(ks + 1) & 1], bfr[(ks + 1) & 1]);
#pragma unroll
            for (int mi = 0; mi < 4; mi++)
#pragma unroll
                for (int ni = 0; ni < 4; ni++)
                    mma_tf32(acc[mi][ni], afr[ks & 1][mi], bfr[ks & 1][ni]);
        }

        if (t + 2 < nt) cp_wait<1>();
        else            cp_wait<0>();
        __syncthreads();
    }

#pragma unroll
    for (int ni = 0; ni < 4; ni++) {
        int c = n0 + wn * 32 + ni * 8 + l4 * 2;
        float b0 = bias[c], b1 = bias[c + 1];
#pragma unroll
        for (int mi = 0; mi < 4; mi++) {
            int r0 = m0 + wm * 64 + mi * 16 + g;
            int r1 = r0 + 8;
            float2 v0 = {acc[mi][ni][0] + b0, acc[mi][ni][1] + b1};
            float2 v1 = {acc[mi][ni][2] + b0, acc[mi][ni][3] + b1};
            if (RELU) {
                v0.x = fmaxf(v0.x, 0.f); v0.y = fmaxf(v0.y, 0.f);
                v1.x = fmaxf(v1.x, 0.f); v1.y = fmaxf(v1.y, 0.f);
            }
            if (ROUND_OUT) {
                v0.x = f2tf32f(v0.x); v0.y = f2tf32f(v0.y);
                v1.x = f2tf32f(v1.x); v1.y = f2tf32f(v1.y);
            }
            *(float2*)(C + (size_t)r0 * N + c) = v0;
            *(float2*)(C + (size_t)r1 * N + c) = v1;
        }
    }
}

// ---------------- warp-per-token residual-add + LayerNorm (+ optional tf32 copy) ----------------
__global__ __launch_bounds__(256) void add_ln_kernel(
    const float* __restrict__ x, const float* __restrict__ a,
    const float* __restrict__ g, const float* __restrict__ b,
    float* __restrict__ dst, float* __restrict__ dst_tf)
{
    int warp = threadIdx.x >> 5, lane = threadIdx.x & 31;
    size_t t = (size_t)blockIdx.x * 8 + warp;

    const float4* xp = (const float4*)(x + t * DMODEL);
    const float4* ap = (const float4*)(a + t * DMODEL);
    float4 v[4];
    float s = 0.f, sq = 0.f;
#pragma unroll
    for (int i = 0; i < 4; i++) {
        float4 xv = xp[lane + 32 * i];
        float4 av = ap[lane + 32 * i];
        xv.x += av.x; xv.y += av.y; xv.z += av.z; xv.w += av.w;
        v[i] = xv;
        s  += xv.x + xv.y + xv.z + xv.w;
        sq += xv.x * xv.x + xv.y * xv.y + xv.z * xv.z + xv.w * xv.w;
    }
#pragma unroll
    for (int o = 16; o > 0; o >>= 1) {
        s  += __shfl_xor_sync(0xffffffffu, s,  o);
        sq += __shfl_xor_sync(0xffffffffu, sq, o);
    }
    float mean = s * (1.f / 512.f);
    float var  = sq * (1.f / 512.f) - mean * mean;
    float rs = rsqrtf(var + 1e-5f);

    float4* dp = (float4*)(dst + t * DMODEL);
    float4* dtp = dst_tf ? (float4*)(dst_tf + t * DMODEL) : (float4*)0;
#pragma unroll
    for (int i = 0; i < 4; i++) {
        float4 gg  = ((const float4*)g)[lane + 32 * i];
        float4 bb2 = ((const float4*)b)[lane + 32 * i];
        float4 o4;
        o4.x = (v[i].x - mean) * rs * gg.x + bb2.x;
        o4.y = (v[i].y - mean) * rs * gg.y + bb2.y;
        o4.z = (v[i].z - mean) * rs * gg.z + bb2.z;
        o4.w = (v[i].w - mean) * rs * gg.w + bb2.w;
        dp[lane + 32 * i] = o4;
        if (dtp) {
            float4 r4;
            r4.x = f2tf32f(o4.x); r4.y = f2tf32f(o4.y);
            r4.z = f2tf32f(o4.z); r4.w = f2tf32f(o4.w);
            dtp[lane + 32 * i] = r4;
        }
    }
}

// ---------------- launcher ----------------
extern "C" void kernel_launch(void* const* d_in, const int* in_sizes, int n_in,
                              void* d_out, int out_size)
{
    const int*   src  = (const int*)d_in[0];
    const int*   mask = (const int*)d_in[1];
    const float* emb = (const float*)d_in[2];
    const float* Wq  = (const float*)d_in[3];
    const float* bq  = (const float*)d_in[4];
    const float* Wk  = (const float*)d_in[5];
    const float* bk  = (const float*)d_in[6];
    const float* Wv  = (const float*)d_in[7];
    const float* bv  = (const float*)d_in[8];
    const float* Wo  = (const float*)d_in[9];
    const float* bo  = (const float*)d_in[10];
    const float* W1  = (const float*)d_in[11];
    const float* b1  = (const float*)d_in[12];
    const float* W2  = (const float*)d_in[13];
    const float* b2  = (const float*)d_in[14];
    const float* ln1g = (const float*)d_in[15];
    const float* ln1b = (const float*)d_in[16];
    const float* ln2g = (const float*)d_in[17];
    const float* ln2b = (const float*)d_in[18];
    float* out = (float*)d_out;

    float *h, *htf, *q, *k, *v, *att, *proj, *ff, *woT, *w1T, *w2T, *wqkvT;
    cudaGetSymbolAddress((void**)&h,    g_h);
    cudaGetSymbolAddress((void**)&htf,  g_htf);
    cudaGetSymbolAddress((void**)&q,    g_q);
    cudaGetSymbolAddress((void**)&k,    g_k);
    cudaGetSymbolAddress((void**)&v,    g_v);
    cudaGetSymbolAddress((void**)&att,  g_att);
    cudaGetSymbolAddress((void**)&proj, g_proj);
    cudaGetSymbolAddress((void**)&ff,   g_ff);
    cudaGetSymbolAddress((void**)&woT,  g_wo_t);
    cudaGetSymbolAddress((void**)&w1T,  g_w1_t);
    cudaGetSymbolAddress((void**)&w2T,  g_w2_t);
    cudaGetSymbolAddress((void**)&wqkvT, g_wqkv_t);

    // flash smem: 2*128*68 + 128*72 + 128*132 + 3*128 + 512 + 128 floats = 178,176 B
    const size_t flashSmem = (size_t)(2 * 128 * QK_LD + 128 * V_LD + 128 * P_LD
                                      + 3 * 128 + 512 + 128) * sizeof(float);
    cudaFuncSetAttribute(flash_kernel, cudaFuncAttributeMaxDynamicSharedMemorySize,
                         (int)flashSmem);
    const size_t gemmSmem = (size_t)3 * 2 * G_STG * sizeof(float);   // 110,592 B
    cudaFuncSetAttribute(sgemm_tf32_pipe<false, false>,
                         cudaFuncAttributeMaxDynamicSharedMemorySize, (int)gemmSmem);
    cudaFuncSetAttribute(sgemm_tf32_pipe<true, true>,
                         cudaFuncAttributeMaxDynamicSharedMemorySize, (int)gemmSmem);
    const size_t qkvSmem = (size_t)(128 + 3 * 64) * QKV_LD * sizeof(float);
    cudaFuncSetAttribute(qkv_mma_kernel, cudaFuncAttributeMaxDynamicSharedMemorySize,
                         (int)qkvSmem);

    // pre-round all GEMM weights to tf32
    {
        int n4;
        n4 = NLAYER * DMODEL * DMODEL / 4;
        round_tf32_kernel<<<(n4 + 255) / 256, 256>>>((const float4*)Wo, (float4*)woT, n4);
        n4 = NLAYER * FDIM * DMODEL / 4;
        round_tf32_kernel<<<(n4 + 255) / 256, 256>>>((const float4*)W1, (float4*)w1T, n4);
        round_tf32_kernel<<<(n4 + 255) / 256, 256>>>((const float4*)W2, (float4*)w2T, n4);
        int nq = NLAYER * HDIM * HDIM / 4;
        pack_qkv_weights_kernel<<<(nq + 255) / 256, 256>>>(
            (const float4*)Wq, (const float4*)Wk, (const float4*)Wv, (float4*)wqkvT);
    }

    embed_kernel<<<T_TOK, 128>>>(src, emb, h, htf);

    for (int l = 0; l < NLAYER; ++l) {
        qkv_mma_kernel<<<256, 256, qkvSmem>>>(htf,
            wqkvT + (size_t)l * 3 * HDIM * HDIM,
            bq + l * HDIM, bk + l * HDIM, bv + l * HDIM,
            q, k, v);

        flash_kernel<<<dim3(16, NHEAD, 2), 256, flashSmem>>>(q, k, v, mask, att);

        sgemm_tf32_pipe<false, false><<<dim3(4, 32), 256, gemmSmem>>>(
            att, woT + (size_t)l * DMODEL * DMODEL, bo + l * DMODEL, proj,
            T_TOK, DMODEL, DMODEL);

        add_ln_kernel<<<T_TOK / 8, 256>>>(h, proj, ln1g + l * DMODEL, ln1b + l * DMODEL,
                                          h, htf);

        sgemm_tf32_pipe<true, true><<<dim3(16, 32), 256, gemmSmem>>>(
            htf, w1T + (size_t)l * FDIM * DMODEL, b1 + l * FDIM, ff,
            T_TOK, FDIM, DMODEL);

        sgemm_tf32_pipe<false, false><<<dim3(4, 32), 256, gemmSmem>>>(
            ff, w2T + (size_t)l * DMODEL * FDIM, b2 + l * DMODEL, proj,
            T_TOK, DMODEL, FDIM);

        add_ln_kernel<<<T_TOK / 8, 256>>>(h, proj, ln2g + l * DMODEL, ln2b + l * DMODEL,
                                          (l == NLAYER - 1) ? out : h,
                                          (l == NLAYER - 1) ? (float*)nullptr : htf);
    }
}